// round 12
// baseline (speedup 1.0000x reference)
#include <cuda_runtime.h>
#include <cuda_bf16.h>
#include <math.h>
#include <stdint.h>

// Problem constants
#define BATCH 2
#define SLEN  2048
#define TCOUNT 4096      // BATCH*SLEN
#define MDIM  1024
#define NHEAD 16
#define DHEAD 64
#define NQKV  3072
#define DFFN  4096
#define NEXP  8
#define NASSIGN 8192     // TCOUNT * TOP_K

// ---------------- scratch (static device globals; no runtime alloc) ----------
__device__ float g_y   [TCOUNT * MDIM];
__device__ float g_h2  [TCOUNT * MDIM];
__device__ float g_u   [NASSIGN * DFFN];
__device__ float g_g3  [NASSIGN * DFFN];
__device__ float g_moe [2 * TCOUNT * MDIM];
__device__ float g_topw[TCOUNT * 2];
__device__ int   g_topi[TCOUNT * 2];
__device__ int   g_cnt [NEXP];
__device__ int   g_base[NEXP];
__device__ int   g_fill[NEXP];
__device__ int   g_assign[NASSIGN];

// bf16 buffers
__device__ __nv_bfloat16 g_qkvb[TCOUNT * NQKV];
__device__ __nv_bfloat16 g_hh  [TCOUNT * MDIM],  g_hl  [TCOUNT * MDIM];
__device__ __nv_bfloat16 g_ctxh[TCOUNT * MDIM],  g_ctxl[TCOUNT * MDIM];
__device__ __nv_bfloat16 g_h2h [TCOUNT * MDIM],  g_h2l [TCOUNT * MDIM];
__device__ __nv_bfloat16 g_acth[NASSIGN * DFFN], g_actl[NASSIGN * DFFN];
__device__ __nv_bfloat16 g_qkvwh[NQKV * MDIM], g_qkvwl[NQKV * MDIM];
__device__ __nv_bfloat16 g_owh[MDIM * MDIM],   g_owl[MDIM * MDIM];
__device__ __nv_bfloat16 g_w1h[NEXP * DFFN * MDIM], g_w1l[NEXP * DFFN * MDIM];
__device__ __nv_bfloat16 g_w3h[NEXP * DFFN * MDIM], g_w3l[NEXP * DFFN * MDIM];
__device__ __nv_bfloat16 g_w2h[NEXP * MDIM * DFFN], g_w2l[NEXP * MDIM * DFFN];

// ---------------- helpers ----------------------------------------------------
__device__ __forceinline__ float warp_sum(float v) {
    #pragma unroll
    for (int o = 16; o; o >>= 1) v += __shfl_xor_sync(0xffffffffu, v, o);
    return v;
}
__device__ __forceinline__ uint32_t smem_u32(const void* p) {
    return (uint32_t)__cvta_generic_to_shared(p);
}
__device__ __forceinline__ void split_bf16(float v, __nv_bfloat16& h, __nv_bfloat16& l) {
    h = __float2bfloat16(v);
    l = __float2bfloat16(v - __bfloat162float(h));
}
__device__ __forceinline__ uint32_t packbf(float a, float b) {
    __nv_bfloat162 t = __floats2bfloat162_rn(a, b);
    return *reinterpret_cast<uint32_t*>(&t);
}
__device__ __forceinline__ void ldsm4(uint32_t* r, uint32_t addr) {
    asm volatile("ldmatrix.sync.aligned.m8n8.x4.shared.b16 {%0,%1,%2,%3}, [%4];"
                 : "=r"(r[0]), "=r"(r[1]), "=r"(r[2]), "=r"(r[3]) : "r"(addr));
}
__device__ __forceinline__ void ldsm4t(uint32_t* r, uint32_t addr) {
    asm volatile("ldmatrix.sync.aligned.m8n8.x4.trans.shared.b16 {%0,%1,%2,%3}, [%4];"
                 : "=r"(r[0]), "=r"(r[1]), "=r"(r[2]), "=r"(r[3]) : "r"(addr));
}
__device__ __forceinline__ void mma_bf16(float* d, const uint32_t* a, const uint32_t* b) {
    asm volatile(
        "mma.sync.aligned.m16n8k16.row.col.f32.bf16.bf16.f32 "
        "{%0,%1,%2,%3}, {%4,%5,%6,%7}, {%8,%9}, {%0,%1,%2,%3};"
        : "+f"(d[0]), "+f"(d[1]), "+f"(d[2]), "+f"(d[3])
        : "r"(a[0]), "r"(a[1]), "r"(a[2]), "r"(a[3]), "r"(b[0]), "r"(b[1]));
}
__device__ __forceinline__ void cp16(uint32_t dst, const void* src) {
    asm volatile("cp.async.cg.shared.global [%0], [%1], 16;" :: "r"(dst), "l"(src));
}
#define CP_COMMIT() asm volatile("cp.async.commit_group;" ::: "memory")
#define CP_WAIT1()  asm volatile("cp.async.wait_group 1;" ::: "memory")
#define CP_WAIT0()  asm volatile("cp.async.wait_group 0;" ::: "memory")

// tile geometry (R8 proven best): CHUNK 32, stride 40 (80 B rows)
#define CHUNK 32
#define TPAD 40
#define TILE_ELT (128 * TPAD)          // 5120 bf16
#define TILE_B   (TILE_ELT * 2)        // 10240 B
#define STAGE_B  (4 * TILE_B)          // 40960 B
#define GSMEM_B  (2 * STAGE_B)         // 81920 B
#define ROW_B    (TPAD * 2)            // 80 B

__device__ __forceinline__ void stage_tile(uint32_t d, const __nv_bfloat16* s) {
    cp16(d, s); cp16(d + 16, s + 8);
}

// ---------------- init --------------------------------------------------------
__global__ void zero_cnt_kernel() {
    if (threadIdx.x < NEXP) g_cnt[threadIdx.x] = 0;
}

// ---------------- merged weight conversion ------------------------------------
__device__ __forceinline__ void cvt_seg(const float* __restrict__ src,
                                        __nv_bfloat16* __restrict__ hi,
                                        __nv_bfloat16* __restrict__ lo, int n,
                                        int gtid, int gstride) {
    for (int i = gtid * 4; i < n; i += gstride) {
        float4 v = *(const float4*)(src + i);
        __nv_bfloat16 h0, h1, h2, h3, l0, l1, l2, l3;
        split_bf16(v.x, h0, l0); split_bf16(v.y, h1, l1);
        split_bf16(v.z, h2, l2); split_bf16(v.w, h3, l3);
        __nv_bfloat162 hh0 = {h0, h1}, hh1 = {h2, h3};
        __nv_bfloat162 ll0 = {l0, l1}, ll1 = {l2, l3};
        *(__nv_bfloat162*)(hi + i)     = hh0;
        *(__nv_bfloat162*)(hi + i + 2) = hh1;
        *(__nv_bfloat162*)(lo + i)     = ll0;
        *(__nv_bfloat162*)(lo + i + 2) = ll1;
    }
}

__global__ void cvt_all_kernel(const float* qkvw, const float* ow,
                               const float* w1, const float* w3, const float* w2) {
    int gtid = blockIdx.x * blockDim.x + threadIdx.x;
    int gstride = gridDim.x * blockDim.x * 4;
    cvt_seg(qkvw, g_qkvwh, g_qkvwl, NQKV * MDIM, gtid, gstride);
    cvt_seg(ow,   g_owh,   g_owl,   MDIM * MDIM, gtid, gstride);
    cvt_seg(w1,   g_w1h,   g_w1l,   NEXP * DFFN * MDIM, gtid, gstride);
    cvt_seg(w3,   g_w3h,   g_w3l,   NEXP * DFFN * MDIM, gtid, gstride);
    cvt_seg(w2,   g_w2h,   g_w2l,   NEXP * MDIM * DFFN, gtid, gstride);
}

// ---------------- LayerNorm ---------------------------------------------------
__global__ void ln_kernel(const float* __restrict__ x,
                          const float* __restrict__ g,
                          const float* __restrict__ b,
                          float* __restrict__ outf,
                          __nv_bfloat16* __restrict__ outh,
                          __nv_bfloat16* __restrict__ outl) {
    int t = blockIdx.x;
    const float* xr = x + (size_t)t * MDIM;
    int tid = threadIdx.x;
    float v[4];
    float s = 0.f, s2 = 0.f;
    #pragma unroll
    for (int i = 0; i < 4; i++) {
        v[i] = xr[tid + 256 * i];
        s += v[i];
        s2 += v[i] * v[i];
    }
    __shared__ float rs[8], rs2[8];
    s = warp_sum(s); s2 = warp_sum(s2);
    if ((tid & 31) == 0) { rs[tid >> 5] = s; rs2[tid >> 5] = s2; }
    __syncthreads();
    if (tid < 32) {
        float a = (tid < 8) ? rs[tid] : 0.f;
        float a2 = (tid < 8) ? rs2[tid] : 0.f;
        a = warp_sum(a); a2 = warp_sum(a2);
        if (tid == 0) { rs[0] = a; rs2[0] = a2; }
    }
    __syncthreads();
    float mean = rs[0] * (1.f / MDIM);
    float var  = rs2[0] * (1.f / MDIM) - mean * mean;
    float inv  = rsqrtf(var + 1e-5f);
    size_t ro = (size_t)t * MDIM;
    #pragma unroll
    for (int i = 0; i < 4; i++) {
        int c = tid + 256 * i;
        float o = (v[i] - mean) * inv * g[c] + b[c];
        if (outf) outf[ro + c] = o;
        __nv_bfloat16 h, l;
        split_bf16(o, h, l);
        outh[ro + c] = h;
        outl[ro + c] = l;
    }
}

// ---------------- pipelined HMMA bf16x3 GEMM ---------------------------------
// MODE 0: +bias, optional +res, fp32 out.
// MODE 1: gather A rows via g_assign, fp32 out.
// MODE 2: A = act rows (base+row), scaled scatter to g_moe.
// MODE 3: +bias, bf16 out (C reinterpreted as __nv_bfloat16*).
template<int MODE>
__global__ void __launch_bounds__(256) hmma_gemm(
    const __nv_bfloat16* __restrict__ Ah_, const __nv_bfloat16* __restrict__ Al_,
    const __nv_bfloat16* __restrict__ Wh_, const __nv_bfloat16* __restrict__ Wl_,
    const float* __restrict__ bias, const float* __restrict__ res,
    float* __restrict__ C, int N, int K)
{
    extern __shared__ __nv_bfloat16 sm[];

    int e = (MODE == 1 || MODE == 2) ? blockIdx.z : 0;
    int cnt = TCOUNT, base = 0;
    if (MODE == 1 || MODE == 2) { cnt = g_cnt[e]; base = g_base[e]; }
    int m0 = blockIdx.y * 128;
    if ((MODE == 1 || MODE == 2) && m0 >= cnt) return;
    int n0 = blockIdx.x * 128;

    const __nv_bfloat16* Wph = Wh_;
    const __nv_bfloat16* Wpl = Wl_;
    if (MODE == 1) { Wph += (size_t)e * DFFN * MDIM; Wpl += (size_t)e * DFFN * MDIM; }
    if (MODE == 2) { Wph += (size_t)e * MDIM * DFFN; Wpl += (size_t)e * MDIM * DFFN; }

    int tid = threadIdx.x;
    int wid = tid >> 5;
    int lane = tid & 31;
    int m0w = (wid & 1) * 64;
    int n0w = (wid >> 1) * 32;

    int crow = tid >> 1;
    int coff = (tid & 1) * 16;
    const __nv_bfloat16 *ah_src, *al_src;
    if (MODE == 0 || MODE == 3) {
        ah_src = Ah_ + (size_t)(m0 + crow) * K + coff;
        al_src = Al_ + (size_t)(m0 + crow) * K + coff;
    } else if (MODE == 1) {
        int lr = m0 + crow; if (lr >= cnt) lr = cnt - 1;
        int tok = g_assign[base + lr] >> 1;
        ah_src = Ah_ + (size_t)tok * K + coff;
        al_src = Al_ + (size_t)tok * K + coff;
    } else {
        int lr = m0 + crow; if (lr >= cnt) lr = cnt - 1;
        ah_src = Ah_ + (size_t)(base + lr) * K + coff;
        al_src = Al_ + (size_t)(base + lr) * K + coff;
    }
    const __nv_bfloat16* bh_src = Wph + (size_t)(n0 + crow) * K + coff;
    const __nv_bfloat16* bl_src = Wpl + (size_t)(n0 + crow) * K + coff;

    uint32_t smb = smem_u32(sm);
    uint32_t ldst = smb + (uint32_t)((crow * TPAD + coff) * 2);

    uint32_t laneA = (uint32_t)(((m0w + (lane & 15)) * TPAD + ((lane >> 4) * 8)) * 2);
    uint32_t laneB = (uint32_t)(((n0w + (lane & 7) + ((lane >> 4) & 1) * 8) * TPAD
                                 + ((lane >> 3) & 1) * 8) * 2);

    float acc[4][4][4];
    #pragma unroll
    for (int i = 0; i < 4; i++)
        #pragma unroll
        for (int j = 0; j < 4; j++)
            #pragma unroll
            for (int r = 0; r < 4; r++) acc[i][j][r] = 0.f;

    int nch = K >> 5;

    {
        uint32_t d = ldst;
        stage_tile(d, ah_src);              stage_tile(d + TILE_B, al_src);
        stage_tile(d + 2 * TILE_B, bh_src); stage_tile(d + 3 * TILE_B, bl_src);
        CP_COMMIT();
    }
    {
        uint32_t d = ldst + STAGE_B;
        stage_tile(d, ah_src + CHUNK);              stage_tile(d + TILE_B, al_src + CHUNK);
        stage_tile(d + 2 * TILE_B, bh_src + CHUNK); stage_tile(d + 3 * TILE_B, bl_src + CHUNK);
        CP_COMMIT();
    }

    for (int c = 0; c < nch; c++) {
        if (c + 1 < nch) CP_WAIT1(); else CP_WAIT0();
        __syncthreads();

        uint32_t sb = smb + (uint32_t)((c & 1) * STAGE_B);
        uint32_t aH = sb + laneA;
        uint32_t aL = sb + TILE_B + laneA;
        uint32_t bH = sb + 2 * TILE_B + laneB;
        uint32_t bL = sb + 3 * TILE_B + laneB;

        #pragma unroll
        for (int ks = 0; ks < 2; ks++) {
            uint32_t koff = (uint32_t)(ks * 32);
            uint32_t bh[4][2], bl[4][2];
            ldsm4(&bh[0][0], bH + koff);
            ldsm4(&bh[2][0], bH + 16 * ROW_B + koff);
            ldsm4(&bl[0][0], bL + koff);
            ldsm4(&bl[2][0], bL + 16 * ROW_B + koff);
            #pragma unroll
            for (int mt = 0; mt < 4; mt++) {
                uint32_t ah[4], al[4];
                ldsm4(ah, aH + (uint32_t)(mt * 16 * ROW_B) + koff);
                ldsm4(al, aL + (uint32_t)(mt * 16 * ROW_B) + koff);
                #pragma unroll
                for (int nt = 0; nt < 4; nt++) mma_bf16(acc[mt][nt], ah, bh[nt]);
                #pragma unroll
                for (int nt = 0; nt < 4; nt++) mma_bf16(acc[mt][nt], ah, bl[nt]);
                #pragma unroll
                for (int nt = 0; nt < 4; nt++) mma_bf16(acc[mt][nt], al, bh[nt]);
            }
        }
        __syncthreads();

        int cn = c + 2;
        if (cn < nch) {
            int kc = cn * CHUNK;
            uint32_t d = ldst + (uint32_t)((cn & 1) * STAGE_B);
            stage_tile(d, ah_src + kc);              stage_tile(d + TILE_B, al_src + kc);
            stage_tile(d + 2 * TILE_B, bh_src + kc); stage_tile(d + 3 * TILE_B, bl_src + kc);
            CP_COMMIT();
        }
    }

    int qrow = lane >> 2;
    int qcol = (lane & 3) * 2;
    #pragma unroll
    for (int mt = 0; mt < 4; mt++) {
        int lm0 = m0 + m0w + mt * 16 + qrow;
        int lm1 = lm0 + 8;
        const float* rr0 = nullptr; const float* rr1 = nullptr;
        float* cr0 = nullptr; float* cr1 = nullptr;
        __nv_bfloat16* cb0 = nullptr; __nv_bfloat16* cb1 = nullptr;
        float sc0 = 1.f, sc1 = 1.f;
        bool live0 = true, live1 = true;
        if (MODE == 0) {
            cr0 = C + (size_t)lm0 * N;
            cr1 = C + (size_t)lm1 * N;
            if (res) { rr0 = res + (size_t)lm0 * N; rr1 = res + (size_t)lm1 * N; }
        } else if (MODE == 3) {
            cb0 = (__nv_bfloat16*)C + (size_t)lm0 * N;
            cb1 = (__nv_bfloat16*)C + (size_t)lm1 * N;
        } else if (MODE == 1) {
            live0 = lm0 < cnt;
            live1 = lm1 < cnt;
            if (live0) cr0 = C + (size_t)(base + lm0) * N;
            if (live1) cr1 = C + (size_t)(base + lm1) * N;
        } else {
            live0 = lm0 < cnt;
            live1 = lm1 < cnt;
            if (live0) {
                int a = g_assign[base + lm0];
                int tok = a >> 1, slot = a & 1;
                sc0 = g_topw[tok * 2 + slot];
                cr0 = g_moe + (size_t)slot * TCOUNT * MDIM + (size_t)tok * N;
            }
            if (live1) {
                int a = g_assign[base + lm1];
                int tok = a >> 1, slot = a & 1;
                sc1 = g_topw[tok * 2 + slot];
                cr1 = g_moe + (size_t)slot * TCOUNT * MDIM + (size_t)tok * N;
            }
        }
        #pragma unroll
        for (int nt = 0; nt < 4; nt++) {
            int col = n0 + n0w + nt * 8 + qcol;
            float2 v0 = make_float2(acc[mt][nt][0], acc[mt][nt][1]);
            float2 v1 = make_float2(acc[mt][nt][2], acc[mt][nt][3]);
            if (MODE == 0 || MODE == 3) {
                float2 bv = *(const float2*)(bias + col);
                v0.x += bv.x; v0.y += bv.y;
                v1.x += bv.x; v1.y += bv.y;
                if (MODE == 0 && res) {
                    float2 r0 = *(const float2*)(rr0 + col);
                    float2 r1 = *(const float2*)(rr1 + col);
                    v0.x += r0.x; v0.y += r0.y;
                    v1.x += r1.x; v1.y += r1.y;
                }
            } else if (MODE == 2) {
                v0.x *= sc0; v0.y *= sc0;
                v1.x *= sc1; v1.y *= sc1;
            }
            if (MODE == 3) {
                *(__nv_bfloat162*)(cb0 + col) = __floats2bfloat162_rn(v0.x, v0.y);
                *(__nv_bfloat162*)(cb1 + col) = __floats2bfloat162_rn(v1.x, v1.y);
            } else {
                if (live0) *(float2*)(cr0 + col) = v0;
                if (live1) *(float2*)(cr1 + col) = v1;
            }
        }
    }
}

// ---------------- tensor-core flash attention (causal, bf16 HMMA) ------------
#define APAD 72

__global__ void __launch_bounds__(256) attn_mma(
    const __nv_bfloat16* __restrict__ qkvb,
    __nv_bfloat16* __restrict__ ctxh,
    __nv_bfloat16* __restrict__ ctxl)
{
    __shared__ __nv_bfloat16 sm[128 * APAD];

    // heavy-first: largest q-tiles (most K-tiles) launch first
    int qt = (int)gridDim.x - 1 - (int)blockIdx.x;
    int h = blockIdx.y, b = blockIdx.z;
    int tid = threadIdx.x, wid = tid >> 5, lane = tid & 31;
    int qbase = qt * 128;
    uint32_t smb = smem_u32(sm);

    {
        int r = tid >> 1, ch = (tid & 1) * 32;
        const __nv_bfloat16* src = qkvb + (size_t)(b * SLEN + qbase + r) * NQKV + h * DHEAD + ch;
        __nv_bfloat16* dst = sm + r * APAD + ch;
        *(uint4*)(dst)      = *(const uint4*)(src);
        *(uint4*)(dst + 8)  = *(const uint4*)(src + 8);
        *(uint4*)(dst + 16) = *(const uint4*)(src + 16);
        *(uint4*)(dst + 24) = *(const uint4*)(src + 24);
    }
    __syncthreads();
    uint32_t qa[4][4];
    #pragma unroll
    for (int ks = 0; ks < 4; ks++) {
        uint32_t addr = smb + (uint32_t)(((wid * 16 + (lane & 15)) * APAD
                                          + ks * 16 + (lane >> 4) * 8) * 2);
        ldsm4(qa[ks], addr);
    }
    __syncthreads();

    __nv_bfloat16* Ks = sm;
    __nv_bfloat16* Vs = sm + 64 * APAD;
    uint32_t smbK = smb;
    uint32_t smbV = smb + 64 * APAD * 2;

    float O[8][4];
    #pragma unroll
    for (int nt = 0; nt < 8; nt++)
        #pragma unroll
        for (int r = 0; r < 4; r++) O[nt][r] = 0.f;
    float m0 = -1e30f, m1 = -1e30f, l0 = 0.f, l1 = 0.f;

    int gmin = qbase + wid * 16;
    int grow0 = gmin + (lane >> 2);
    int nkt = 2 * qt + 2;

    for (int jt = 0; jt < nkt; jt++) {
        int kb = jt * 64;
        {
            int r = tid >> 2, c = (tid & 3) * 16;
            size_t trow = (size_t)(b * SLEN + kb + r) * NQKV + h * DHEAD + c;
            *(uint4*)(Ks + r * APAD + c)     = *(const uint4*)(qkvb + trow + MDIM);
            *(uint4*)(Ks + r * APAD + c + 8) = *(const uint4*)(qkvb + trow + MDIM + 8);
            *(uint4*)(Vs + r * APAD + c)     = *(const uint4*)(qkvb + trow + 2 * MDIM);
            *(uint4*)(Vs + r * APAD + c + 8) = *(const uint4*)(qkvb + trow + 2 * MDIM + 8);
        }
        __syncthreads();

        bool skip = kb > gmin + 15;
        if (!skip) {
            float S[8][4];
            #pragma unroll
            for (int nt = 0; nt < 8; nt++)
                #pragma unroll
                for (int r = 0; r < 4; r++) S[nt][r] = 0.f;
            #pragma unroll
            for (int ks = 0; ks < 4; ks++) {
                #pragma unroll
                for (int np = 0; np < 4; np++) {
                    uint32_t bb[4];
                    uint32_t addr = smbK + (uint32_t)(((np * 16 + (lane & 7)
                                      + ((lane >> 4) & 1) * 8) * APAD
                                      + ks * 16 + ((lane >> 3) & 1) * 8) * 2);
                    ldsm4(bb, addr);
                    mma_bf16(S[2 * np],     qa[ks], bb);
                    mma_bf16(S[2 * np + 1], qa[ks], bb + 2);
                }
            }
            if (kb + 63 > gmin) {
                #pragma unroll
                for (int nt = 0; nt < 8; nt++) {
                    int gc = kb + nt * 8 + (lane & 3) * 2;
                    if (gc     > grow0)     S[nt][0] = -1e30f;
                    if (gc + 1 > grow0)     S[nt][1] = -1e30f;
                    if (gc     > grow0 + 8) S[nt][2] = -1e30f;
                    if (gc + 1 > grow0 + 8) S[nt][3] = -1e30f;
                }
            }
            float tm0 = -1e30f, tm1 = -1e30f;
            #pragma unroll
            for (int nt = 0; nt < 8; nt++) {
                tm0 = fmaxf(tm0, fmaxf(S[nt][0], S[nt][1]));
                tm1 = fmaxf(tm1, fmaxf(S[nt][2], S[nt][3]));
            }
            tm0 = fmaxf(tm0, __shfl_xor_sync(0xffffffffu, tm0, 1));
            tm0 = fmaxf(tm0, __shfl_xor_sync(0xffffffffu, tm0, 2));
            tm1 = fmaxf(tm1, __shfl_xor_sync(0xffffffffu, tm1, 1));
            tm1 = fmaxf(tm1, __shfl_xor_sync(0xffffffffu, tm1, 2));
            float nm0 = fmaxf(m0, tm0), nm1 = fmaxf(m1, tm1);
            float sc0 = __expf(m0 - nm0), sc1 = __expf(m1 - nm1);
            float rs0 = 0.f, rs1 = 0.f;
            #pragma unroll
            for (int nt = 0; nt < 8; nt++) {
                S[nt][0] = __expf(S[nt][0] - nm0);
                S[nt][1] = __expf(S[nt][1] - nm0);
                S[nt][2] = __expf(S[nt][2] - nm1);
                S[nt][3] = __expf(S[nt][3] - nm1);
                rs0 += S[nt][0] + S[nt][1];
                rs1 += S[nt][2] + S[nt][3];
            }
            rs0 += __shfl_xor_sync(0xffffffffu, rs0, 1);
            rs0 += __shfl_xor_sync(0xffffffffu, rs0, 2);
            rs1 += __shfl_xor_sync(0xffffffffu, rs1, 1);
            rs1 += __shfl_xor_sync(0xffffffffu, rs1, 2);
            l0 = l0 * sc0 + rs0; l1 = l1 * sc1 + rs1;
            m0 = nm0; m1 = nm1;
            #pragma unroll
            for (int nt = 0; nt < 8; nt++) {
                O[nt][0] *= sc0; O[nt][1] *= sc0;
                O[nt][2] *= sc1; O[nt][3] *= sc1;
            }
            uint32_t pa[4][4];
            #pragma unroll
            for (int ks = 0; ks < 4; ks++) {
                pa[ks][0] = packbf(S[2 * ks][0],     S[2 * ks][1]);
                pa[ks][1] = packbf(S[2 * ks][2],     S[2 * ks][3]);
                pa[ks][2] = packbf(S[2 * ks + 1][0], S[2 * ks + 1][1]);
                pa[ks][3] = packbf(S[2 * ks + 1][2], S[2 * ks + 1][3]);
            }
            #pragma unroll
            for (int ks = 0; ks < 4; ks++) {
                #pragma unroll
                for (int np = 0; np < 4; np++) {
                    uint32_t bv[4];
                    uint32_t addr = smbV + (uint32_t)(((ks * 16 + (lane & 15)) * APAD
                                      + np * 16 + (lane >> 4) * 8) * 2);
                    ldsm4t(bv, addr);
                    mma_bf16(O[2 * np],     pa[ks], bv);
                    mma_bf16(O[2 * np + 1], pa[ks], bv + 2);
                }
            }
        }
        __syncthreads();
    }

    float inv0 = 1.f / l0, inv1 = 1.f / l1;
    size_t tok0 = (size_t)(b * SLEN + qbase + wid * 16 + (lane >> 2));
    #pragma unroll
    for (int nt = 0; nt < 8; nt++) {
        int col = h * DHEAD + nt * 8 + (lane & 3) * 2;
        float v0 = O[nt][0] * inv0, v1 = O[nt][1] * inv0;
        float v2 = O[nt][2] * inv1, v3 = O[nt][3] * inv1;
        __nv_bfloat16 h0, h1, h2, h3, q0, q1, q2, q3;
        split_bf16(v0, h0, q0); split_bf16(v1, h1, q1);
        split_bf16(v2, h2, q2); split_bf16(v3, h3, q3);
        __nv_bfloat162 ph0 = {h0, h1}, pl0 = {q0, q1};
        __nv_bfloat162 ph1 = {h2, h3}, pl1 = {q2, q3};
        *(__nv_bfloat162*)(ctxh + tok0 * MDIM + col)       = ph0;
        *(__nv_bfloat162*)(ctxl + tok0 * MDIM + col)       = pl0;
        *(__nv_bfloat162*)(ctxh + (tok0 + 8) * MDIM + col) = ph1;
        *(__nv_bfloat162*)(ctxl + (tok0 + 8) * MDIM + col) = pl1;
    }
}

// ---------------- routing ----------------------------------------------------
__global__ void route_kernel(const float* __restrict__ h2,
                             const float* __restrict__ gw) {
    int t = blockIdx.x * 8 + (threadIdx.x >> 5);
    int lane = threadIdx.x & 31;
    if (t >= TCOUNT) return;
    const float* hr = h2 + (size_t)t * MDIM;
    float acc[NEXP];
    #pragma unroll
    for (int e = 0; e < NEXP; e++) acc[e] = 0.f;
    for (int i = lane; i < MDIM; i += 32) {
        float hv = hr[i];
        #pragma unroll
        for (int e = 0; e < NEXP; e++) acc[e] += hv * gw[e * MDIM + i];
    }
    #pragma unroll
    for (int e = 0; e < NEXP; e++) acc[e] = warp_sum(acc[e]);
    if (lane == 0) {
        float mx = acc[0];
        #pragma unroll
        for (int e = 1; e < NEXP; e++) mx = fmaxf(mx, acc[e]);
        float ex[NEXP];
        #pragma unroll
        for (int e = 0; e < NEXP; e++) ex[e] = __expf(acc[e] - mx);
        int i0 = 0;
        #pragma unroll
        for (int e = 1; e < NEXP; e++) if (acc[e] > acc[i0]) i0 = e;
        int i1 = (i0 == 0) ? 1 : 0;
        #pragma unroll
        for (int e = 0; e < NEXP; e++)
            if (e != i0 && acc[e] > acc[i1]) i1 = e;
        float denom = 1.f / (ex[i0] + ex[i1]);
        g_topi[t * 2 + 0] = i0;
        g_topi[t * 2 + 1] = i1;
        g_topw[t * 2 + 0] = ex[i0] * denom;
        g_topw[t * 2 + 1] = ex[i1] * denom;
        atomicAdd(&g_cnt[i0], 1);
        atomicAdd(&g_cnt[i1], 1);
    }
}

__global__ void prefix_kernel() {
    if (threadIdx.x == 0 && blockIdx.x == 0) {
        int acc = 0;
        for (int e = 0; e < NEXP; e++) {
            g_base[e] = acc;
            acc += g_cnt[e];
            g_fill[e] = 0;
        }
    }
}

__global__ void assign_kernel() {
    int t = blockIdx.x * blockDim.x + threadIdx.x;
    if (t < TCOUNT) {
        #pragma unroll
        for (int s = 0; s < 2; s++) {
            int e = g_topi[t * 2 + s];
            int pos = g_base[e] + atomicAdd(&g_fill[e], 1);
            g_assign[pos] = t * 2 + s;
        }
    }
}

// ---------------- elementwise -------------------------------------------------
__global__ void silu_mul_kernel(const float* __restrict__ u,
                                const float* __restrict__ g3,
                                __nv_bfloat16* __restrict__ acth,
                                __nv_bfloat16* __restrict__ actl, int n) {
    for (int i = blockIdx.x * blockDim.x + threadIdx.x; i < n;
         i += gridDim.x * blockDim.x) {
        float a = u[i];
        float s = a / (1.f + __expf(-a));
        float v = s * g3[i];
        __nv_bfloat16 h, l;
        split_bf16(v, h, l);
        acth[i] = h;
        actl[i] = l;
    }
}

__global__ void final_add_kernel(const float* __restrict__ y,
                                 float* __restrict__ out, int n) {
    for (int i = blockIdx.x * blockDim.x + threadIdx.x; i < n;
         i += gridDim.x * blockDim.x) {
        out[i] = y[i] + g_moe[i] + g_moe[(size_t)TCOUNT * MDIM + i];
    }
}

// ---------------- launch ------------------------------------------------------
extern "C" void kernel_launch(void* const* d_in, const int* in_sizes, int n_in,
                              void* d_out, int out_size) {
    const float* x     = (const float*)d_in[0];
    const float* ln1g  = (const float*)d_in[1];
    const float* ln1b  = (const float*)d_in[2];
    const float* qkvw  = (const float*)d_in[3];
    const float* qkvb  = (const float*)d_in[4];
    const float* ow    = (const float*)d_in[5];
    const float* ob    = (const float*)d_in[6];
    const float* ln2g  = (const float*)d_in[7];
    const float* ln2b  = (const float*)d_in[8];
    const float* gatew = (const float*)d_in[9];
    const float* w1    = (const float*)d_in[10];
    const float* w2    = (const float*)d_in[11];
    const float* w3    = (const float*)d_in[12];
    float* out = (float*)d_out;

    cudaFuncSetAttribute(hmma_gemm<0>,
                         cudaFuncAttributeMaxDynamicSharedMemorySize, GSMEM_B);
    cudaFuncSetAttribute(hmma_gemm<1>,
                         cudaFuncAttributeMaxDynamicSharedMemorySize, GSMEM_B);
    cudaFuncSetAttribute(hmma_gemm<2>,
                         cudaFuncAttributeMaxDynamicSharedMemorySize, GSMEM_B);
    cudaFuncSetAttribute(hmma_gemm<3>,
                         cudaFuncAttributeMaxDynamicSharedMemorySize, GSMEM_B);

    void *hh, *hl, *ctxh, *ctxl, *h2h, *h2l, *acth, *actl, *qkvbp;
    void *qwh, *qwl, *owh, *owl, *w1h, *w1l, *w3h, *w3l, *w2h, *w2l;
    cudaGetSymbolAddress(&hh, g_hh);     cudaGetSymbolAddress(&hl, g_hl);
    cudaGetSymbolAddress(&ctxh, g_ctxh); cudaGetSymbolAddress(&ctxl, g_ctxl);
    cudaGetSymbolAddress(&h2h, g_h2h);   cudaGetSymbolAddress(&h2l, g_h2l);
    cudaGetSymbolAddress(&acth, g_acth); cudaGetSymbolAddress(&actl, g_actl);
    cudaGetSymbolAddress(&qkvbp, g_qkvb);
    cudaGetSymbolAddress(&qwh, g_qkvwh); cudaGetSymbolAddress(&qwl, g_qkvwl);
    cudaGetSymbolAddress(&owh, g_owh);   cudaGetSymbolAddress(&owl, g_owl);
    cudaGetSymbolAddress(&w1h, g_w1h);   cudaGetSymbolAddress(&w1l, g_w1l);
    cudaGetSymbolAddress(&w3h, g_w3h);   cudaGetSymbolAddress(&w3l, g_w3l);
    cudaGetSymbolAddress(&w2h, g_w2h);   cudaGetSymbolAddress(&w2l, g_w2l);
    void *yp, *h2p, *up, *g3p;
    cudaGetSymbolAddress(&yp, g_y);
    cudaGetSymbolAddress(&h2p, g_h2);
    cudaGetSymbolAddress(&up, g_u);
    cudaGetSymbolAddress(&g3p, g_g3);

    // Launch order is deliberate: with ncu -s 5 -c 1, the captured launch is
    // index 5 = the O-projection GEMM (hmma_gemm<0>), a representative GEMM.
    // (0) zero counters
    zero_cnt_kernel<<<1, 32>>>();
    // (1) all weight conversions in one launch
    cvt_all_kernel<<<8192, 256>>>(qkvw, ow, w1, w3, w2);
    // (2) h = LN1(x) -> bf16 hi/lo
    ln_kernel<<<TCOUNT, 256>>>(x, ln1g, ln1b, nullptr,
                               (__nv_bfloat16*)hh, (__nv_bfloat16*)hl);
    // (3) qkv = h @ qkvw^T + qkvb -> bf16 directly
    hmma_gemm<3><<<dim3(NQKV / 128, TCOUNT / 128), 256, GSMEM_B>>>(
        (__nv_bfloat16*)hh, (__nv_bfloat16*)hl,
        (__nv_bfloat16*)qwh, (__nv_bfloat16*)qwl,
        qkvb, nullptr, (float*)qkvbp, NQKV, MDIM);
    // (4) tensor-core causal flash attention -> ctx hi/lo
    attn_mma<<<dim3(SLEN / 128, NHEAD, BATCH), 256>>>(
        (__nv_bfloat16*)qkvbp, (__nv_bfloat16*)ctxh, (__nv_bfloat16*)ctxl);
    // (5) y = x + ctx @ ow^T + ob    <-- ncu capture target
    hmma_gemm<0><<<dim3(MDIM / 128, TCOUNT / 128), 256, GSMEM_B>>>(
        (__nv_bfloat16*)ctxh, (__nv_bfloat16*)ctxl,
        (__nv_bfloat16*)owh, (__nv_bfloat16*)owl,
        ob, x, (float*)yp, MDIM, MDIM);
    // (6) h2 = LN2(y) -> fp32 + bf16 hi/lo
    ln_kernel<<<TCOUNT, 256>>>((float*)yp, ln2g, ln2b, (float*)h2p,
                               (__nv_bfloat16*)h2h, (__nv_bfloat16*)h2l);
    // (7-9) routing
    route_kernel<<<TCOUNT / 8, 256>>>((float*)h2p, gatew);
    prefix_kernel<<<1, 32>>>();
    assign_kernel<<<TCOUNT / 256, 256>>>();
    // (10,11) u = h2g @ w1^T ; g3 = h2g @ w3^T
    hmma_gemm<1><<<dim3(DFFN / 128, NASSIGN / 128, NEXP), 256, GSMEM_B>>>(
        (__nv_bfloat16*)h2h, (__nv_bfloat16*)h2l,
        (__nv_bfloat16*)w1h, (__nv_bfloat16*)w1l,
        nullptr, nullptr, (float*)up, DFFN, MDIM);
    hmma_gemm<1><<<dim3(DFFN / 128, NASSIGN / 128, NEXP), 256, GSMEM_B>>>(
        (__nv_bfloat16*)h2h, (__nv_bfloat16*)h2l,
        (__nv_bfloat16*)w3h, (__nv_bfloat16*)w3l,
        nullptr, nullptr, (float*)g3p, DFFN, MDIM);
    // (12) act = silu(u) * g3 -> bf16 hi/lo
    silu_mul_kernel<<<4096, 256>>>((float*)up, (float*)g3p,
                                   (__nv_bfloat16*)acth, (__nv_bfloat16*)actl,
                                   NASSIGN * DFFN);
    // (13) moe scatter: w * (act @ w2^T)
    hmma_gemm<2><<<dim3(MDIM / 128, NASSIGN / 128, NEXP), 256, GSMEM_B>>>(
        (__nv_bfloat16*)acth, (__nv_bfloat16*)actl,
        (__nv_bfloat16*)w2h, (__nv_bfloat16*)w2l,
        nullptr, nullptr, nullptr, MDIM, DFFN);
    // (14) out = y + moe0 + moe1
    final_add_kernel<<<4096, 256>>>((float*)yp, out, TCOUNT * MDIM);
}

// round 16
// speedup vs baseline: 1.1548x; 1.1548x over previous
#include <cuda_runtime.h>
#include <cuda_bf16.h>
#include <math.h>
#include <stdint.h>

// Problem constants
#define BATCH 2
#define SLEN  2048
#define TCOUNT 4096      // BATCH*SLEN
#define MDIM  1024
#define NHEAD 16
#define DHEAD 64
#define NQKV  3072
#define DFFN  4096
#define NEXP  8
#define NASSIGN 8192     // TCOUNT * TOP_K

// ---------------- scratch (static device globals; no runtime alloc) ----------
__device__ float g_y   [TCOUNT * MDIM];
__device__ float g_h2  [TCOUNT * MDIM];
__device__ float g_u   [NASSIGN * DFFN];
__device__ float g_g3  [NASSIGN * DFFN];
__device__ float g_moe [2 * TCOUNT * MDIM];
__device__ float g_topw[TCOUNT * 2];
__device__ int   g_topi[TCOUNT * 2];
__device__ int   g_cnt [NEXP];
__device__ int   g_base[NEXP];
__device__ int   g_fill[NEXP];
__device__ int   g_assign[NASSIGN];

// bf16 buffers
__device__ __nv_bfloat16 g_qkvb[TCOUNT * NQKV];
__device__ __nv_bfloat16 g_hh  [TCOUNT * MDIM],  g_hl  [TCOUNT * MDIM];
__device__ __nv_bfloat16 g_ctxh[TCOUNT * MDIM],  g_ctxl[TCOUNT * MDIM];
__device__ __nv_bfloat16 g_h2h [TCOUNT * MDIM],  g_h2l [TCOUNT * MDIM];
__device__ __nv_bfloat16 g_acth[NASSIGN * DFFN], g_actl[NASSIGN * DFFN];
__device__ __nv_bfloat16 g_qkvwh[NQKV * MDIM], g_qkvwl[NQKV * MDIM];
__device__ __nv_bfloat16 g_owh[MDIM * MDIM],   g_owl[MDIM * MDIM];
__device__ __nv_bfloat16 g_w1h[NEXP * DFFN * MDIM], g_w1l[NEXP * DFFN * MDIM];
__device__ __nv_bfloat16 g_w3h[NEXP * DFFN * MDIM], g_w3l[NEXP * DFFN * MDIM];
__device__ __nv_bfloat16 g_w2h[NEXP * MDIM * DFFN], g_w2l[NEXP * MDIM * DFFN];

// ---------------- helpers ----------------------------------------------------
__device__ __forceinline__ float warp_sum(float v) {
    #pragma unroll
    for (int o = 16; o; o >>= 1) v += __shfl_xor_sync(0xffffffffu, v, o);
    return v;
}
__device__ __forceinline__ uint32_t smem_u32(const void* p) {
    return (uint32_t)__cvta_generic_to_shared(p);
}
__device__ __forceinline__ void split_bf16(float v, __nv_bfloat16& h, __nv_bfloat16& l) {
    h = __float2bfloat16(v);
    l = __float2bfloat16(v - __bfloat162float(h));
}
__device__ __forceinline__ uint32_t packbf(float a, float b) {
    __nv_bfloat162 t = __floats2bfloat162_rn(a, b);
    return *reinterpret_cast<uint32_t*>(&t);
}
__device__ __forceinline__ void ldsm4(uint32_t* r, uint32_t addr) {
    asm volatile("ldmatrix.sync.aligned.m8n8.x4.shared.b16 {%0,%1,%2,%3}, [%4];"
                 : "=r"(r[0]), "=r"(r[1]), "=r"(r[2]), "=r"(r[3]) : "r"(addr));
}
__device__ __forceinline__ void ldsm4t(uint32_t* r, uint32_t addr) {
    asm volatile("ldmatrix.sync.aligned.m8n8.x4.trans.shared.b16 {%0,%1,%2,%3}, [%4];"
                 : "=r"(r[0]), "=r"(r[1]), "=r"(r[2]), "=r"(r[3]) : "r"(addr));
}
__device__ __forceinline__ void mma_bf16(float* d, const uint32_t* a, const uint32_t* b) {
    asm volatile(
        "mma.sync.aligned.m16n8k16.row.col.f32.bf16.bf16.f32 "
        "{%0,%1,%2,%3}, {%4,%5,%6,%7}, {%8,%9}, {%0,%1,%2,%3};"
        : "+f"(d[0]), "+f"(d[1]), "+f"(d[2]), "+f"(d[3])
        : "r"(a[0]), "r"(a[1]), "r"(a[2]), "r"(a[3]), "r"(b[0]), "r"(b[1]));
}
__device__ __forceinline__ void cp16(uint32_t dst, const void* src) {
    asm volatile("cp.async.cg.shared.global [%0], [%1], 16;" :: "r"(dst), "l"(src));
}
#define CP_COMMIT() asm volatile("cp.async.commit_group;" ::: "memory")
#define CP_WAIT1()  asm volatile("cp.async.wait_group 1;" ::: "memory")
#define CP_WAIT0()  asm volatile("cp.async.wait_group 0;" ::: "memory")

// tile geometry (R8 proven best): CHUNK 32, stride 40 (80 B rows)
#define CHUNK 32
#define TPAD 40
#define TILE_ELT (128 * TPAD)          // 5120 bf16
#define TILE_B   (TILE_ELT * 2)        // 10240 B
#define STAGE_B  (4 * TILE_B)          // 40960 B
#define GSMEM_B  (2 * STAGE_B)         // 81920 B
#define ROW_B    (TPAD * 2)            // 80 B

__device__ __forceinline__ void stage_tile(uint32_t d, const __nv_bfloat16* s) {
    cp16(d, s); cp16(d + 16, s + 8);
}

// ---------------- init --------------------------------------------------------
__global__ void zero_cnt_kernel() {
    if (threadIdx.x < NEXP) g_cnt[threadIdx.x] = 0;
}

// ---------------- merged weight conversion ------------------------------------
__device__ __forceinline__ void cvt_seg(const float* __restrict__ src,
                                        __nv_bfloat16* __restrict__ hi,
                                        __nv_bfloat16* __restrict__ lo, int n,
                                        int gtid, int gstride) {
    for (int i = gtid * 4; i < n; i += gstride) {
        float4 v = *(const float4*)(src + i);
        __nv_bfloat16 h0, h1, h2, h3, l0, l1, l2, l3;
        split_bf16(v.x, h0, l0); split_bf16(v.y, h1, l1);
        split_bf16(v.z, h2, l2); split_bf16(v.w, h3, l3);
        __nv_bfloat162 hh0 = {h0, h1}, hh1 = {h2, h3};
        __nv_bfloat162 ll0 = {l0, l1}, ll1 = {l2, l3};
        *(__nv_bfloat162*)(hi + i)     = hh0;
        *(__nv_bfloat162*)(hi + i + 2) = hh1;
        *(__nv_bfloat162*)(lo + i)     = ll0;
        *(__nv_bfloat162*)(lo + i + 2) = ll1;
    }
}

__global__ void cvt_all_kernel(const float* qkvw, const float* ow,
                               const float* w1, const float* w3, const float* w2) {
    int gtid = blockIdx.x * blockDim.x + threadIdx.x;
    int gstride = gridDim.x * blockDim.x * 4;
    cvt_seg(qkvw, g_qkvwh, g_qkvwl, NQKV * MDIM, gtid, gstride);
    cvt_seg(ow,   g_owh,   g_owl,   MDIM * MDIM, gtid, gstride);
    cvt_seg(w1,   g_w1h,   g_w1l,   NEXP * DFFN * MDIM, gtid, gstride);
    cvt_seg(w3,   g_w3h,   g_w3l,   NEXP * DFFN * MDIM, gtid, gstride);
    cvt_seg(w2,   g_w2h,   g_w2l,   NEXP * MDIM * DFFN, gtid, gstride);
}

// ---------------- LayerNorm ---------------------------------------------------
__global__ void ln_kernel(const float* __restrict__ x,
                          const float* __restrict__ g,
                          const float* __restrict__ b,
                          float* __restrict__ outf,
                          __nv_bfloat16* __restrict__ outh,
                          __nv_bfloat16* __restrict__ outl) {
    int t = blockIdx.x;
    const float* xr = x + (size_t)t * MDIM;
    int tid = threadIdx.x;
    float v[4];
    float s = 0.f, s2 = 0.f;
    #pragma unroll
    for (int i = 0; i < 4; i++) {
        v[i] = xr[tid + 256 * i];
        s += v[i];
        s2 += v[i] * v[i];
    }
    __shared__ float rs[8], rs2[8];
    s = warp_sum(s); s2 = warp_sum(s2);
    if ((tid & 31) == 0) { rs[tid >> 5] = s; rs2[tid >> 5] = s2; }
    __syncthreads();
    if (tid < 32) {
        float a = (tid < 8) ? rs[tid] : 0.f;
        float a2 = (tid < 8) ? rs2[tid] : 0.f;
        a = warp_sum(a); a2 = warp_sum(a2);
        if (tid == 0) { rs[0] = a; rs2[0] = a2; }
    }
    __syncthreads();
    float mean = rs[0] * (1.f / MDIM);
    float var  = rs2[0] * (1.f / MDIM) - mean * mean;
    float inv  = rsqrtf(var + 1e-5f);
    size_t ro = (size_t)t * MDIM;
    #pragma unroll
    for (int i = 0; i < 4; i++) {
        int c = tid + 256 * i;
        float o = (v[i] - mean) * inv * g[c] + b[c];
        if (outf) outf[ro + c] = o;
        __nv_bfloat16 h, l;
        split_bf16(o, h, l);
        outh[ro + c] = h;
        outl[ro + c] = l;
    }
}

// ---------------- pipelined HMMA bf16x3 GEMM ---------------------------------
// __launch_bounds__(256, 2): force 2 CTAs/SM (regs capped ~124) — R12 profile
// showed occ 22.9% (1 CTA) with tensor pipe at only 48.8%.
// MODE 0: +bias, optional +res, fp32 out.
// MODE 1: gather A rows via g_assign, fp32 out.
// MODE 2: A = act rows (base+row), scaled scatter to g_moe.
// MODE 3: +bias, bf16 out (C reinterpreted as __nv_bfloat16*).
template<int MODE>
__global__ void __launch_bounds__(256, 2) hmma_gemm(
    const __nv_bfloat16* __restrict__ Ah_, const __nv_bfloat16* __restrict__ Al_,
    const __nv_bfloat16* __restrict__ Wh_, const __nv_bfloat16* __restrict__ Wl_,
    const float* __restrict__ bias, const float* __restrict__ res,
    float* __restrict__ C, int N, int K)
{
    extern __shared__ __nv_bfloat16 sm[];

    int e = (MODE == 1 || MODE == 2) ? blockIdx.z : 0;
    int cnt = TCOUNT, base = 0;
    if (MODE == 1 || MODE == 2) { cnt = g_cnt[e]; base = g_base[e]; }
    int m0 = blockIdx.y * 128;
    if ((MODE == 1 || MODE == 2) && m0 >= cnt) return;
    int n0 = blockIdx.x * 128;

    const __nv_bfloat16* Wph = Wh_;
    const __nv_bfloat16* Wpl = Wl_;
    if (MODE == 1) { Wph += (size_t)e * DFFN * MDIM; Wpl += (size_t)e * DFFN * MDIM; }
    if (MODE == 2) { Wph += (size_t)e * MDIM * DFFN; Wpl += (size_t)e * MDIM * DFFN; }

    int tid = threadIdx.x;
    int wid = tid >> 5;
    int lane = tid & 31;
    int m0w = (wid & 1) * 64;
    int n0w = (wid >> 1) * 32;

    int crow = tid >> 1;
    int coff = (tid & 1) * 16;
    const __nv_bfloat16 *ah_src, *al_src;
    if (MODE == 0 || MODE == 3) {
        ah_src = Ah_ + (size_t)(m0 + crow) * K + coff;
        al_src = Al_ + (size_t)(m0 + crow) * K + coff;
    } else if (MODE == 1) {
        int lr = m0 + crow; if (lr >= cnt) lr = cnt - 1;
        int tok = g_assign[base + lr] >> 1;
        ah_src = Ah_ + (size_t)tok * K + coff;
        al_src = Al_ + (size_t)tok * K + coff;
    } else {
        int lr = m0 + crow; if (lr >= cnt) lr = cnt - 1;
        ah_src = Ah_ + (size_t)(base + lr) * K + coff;
        al_src = Al_ + (size_t)(base + lr) * K + coff;
    }
    const __nv_bfloat16* bh_src = Wph + (size_t)(n0 + crow) * K + coff;
    const __nv_bfloat16* bl_src = Wpl + (size_t)(n0 + crow) * K + coff;

    uint32_t smb = smem_u32(sm);
    uint32_t ldst = smb + (uint32_t)((crow * TPAD + coff) * 2);

    uint32_t laneA = (uint32_t)(((m0w + (lane & 15)) * TPAD + ((lane >> 4) * 8)) * 2);
    uint32_t laneB = (uint32_t)(((n0w + (lane & 7) + ((lane >> 4) & 1) * 8) * TPAD
                                 + ((lane >> 3) & 1) * 8) * 2);

    float acc[4][4][4];
    #pragma unroll
    for (int i = 0; i < 4; i++)
        #pragma unroll
        for (int j = 0; j < 4; j++)
            #pragma unroll
            for (int r = 0; r < 4; r++) acc[i][j][r] = 0.f;

    int nch = K >> 5;

    {
        uint32_t d = ldst;
        stage_tile(d, ah_src);              stage_tile(d + TILE_B, al_src);
        stage_tile(d + 2 * TILE_B, bh_src); stage_tile(d + 3 * TILE_B, bl_src);
        CP_COMMIT();
    }
    {
        uint32_t d = ldst + STAGE_B;
        stage_tile(d, ah_src + CHUNK);              stage_tile(d + TILE_B, al_src + CHUNK);
        stage_tile(d + 2 * TILE_B, bh_src + CHUNK); stage_tile(d + 3 * TILE_B, bl_src + CHUNK);
        CP_COMMIT();
    }

    for (int c = 0; c < nch; c++) {
        if (c + 1 < nch) CP_WAIT1(); else CP_WAIT0();
        __syncthreads();

        uint32_t sb = smb + (uint32_t)((c & 1) * STAGE_B);
        uint32_t aH = sb + laneA;
        uint32_t aL = sb + TILE_B + laneA;
        uint32_t bH = sb + 2 * TILE_B + laneB;
        uint32_t bL = sb + 3 * TILE_B + laneB;

        #pragma unroll
        for (int ks = 0; ks < 2; ks++) {
            uint32_t koff = (uint32_t)(ks * 32);
            uint32_t bh[4][2], bl[4][2];
            ldsm4(&bh[0][0], bH + koff);
            ldsm4(&bh[2][0], bH + 16 * ROW_B + koff);
            ldsm4(&bl[0][0], bL + koff);
            ldsm4(&bl[2][0], bL + 16 * ROW_B + koff);
            #pragma unroll
            for (int mt = 0; mt < 4; mt++) {
                uint32_t ah[4], al[4];
                ldsm4(ah, aH + (uint32_t)(mt * 16 * ROW_B) + koff);
                ldsm4(al, aL + (uint32_t)(mt * 16 * ROW_B) + koff);
                #pragma unroll
                for (int nt = 0; nt < 4; nt++) mma_bf16(acc[mt][nt], ah, bh[nt]);
                #pragma unroll
                for (int nt = 0; nt < 4; nt++) mma_bf16(acc[mt][nt], ah, bl[nt]);
                #pragma unroll
                for (int nt = 0; nt < 4; nt++) mma_bf16(acc[mt][nt], al, bh[nt]);
            }
        }
        __syncthreads();

        int cn = c + 2;
        if (cn < nch) {
            int kc = cn * CHUNK;
            uint32_t d = ldst + (uint32_t)((cn & 1) * STAGE_B);
            stage_tile(d, ah_src + kc);              stage_tile(d + TILE_B, al_src + kc);
            stage_tile(d + 2 * TILE_B, bh_src + kc); stage_tile(d + 3 * TILE_B, bl_src + kc);
            CP_COMMIT();
        }
    }

    int qrow = lane >> 2;
    int qcol = (lane & 3) * 2;
    #pragma unroll
    for (int mt = 0; mt < 4; mt++) {
        int lm0 = m0 + m0w + mt * 16 + qrow;
        int lm1 = lm0 + 8;
        const float* rr0 = nullptr; const float* rr1 = nullptr;
        float* cr0 = nullptr; float* cr1 = nullptr;
        __nv_bfloat16* cb0 = nullptr; __nv_bfloat16* cb1 = nullptr;
        float sc0 = 1.f, sc1 = 1.f;
        bool live0 = true, live1 = true;
        if (MODE == 0) {
            cr0 = C + (size_t)lm0 * N;
            cr1 = C + (size_t)lm1 * N;
            if (res) { rr0 = res + (size_t)lm0 * N; rr1 = res + (size_t)lm1 * N; }
        } else if (MODE == 3) {
            cb0 = (__nv_bfloat16*)C + (size_t)lm0 * N;
            cb1 = (__nv_bfloat16*)C + (size_t)lm1 * N;
        } else if (MODE == 1) {
            live0 = lm0 < cnt;
            live1 = lm1 < cnt;
            if (live0) cr0 = C + (size_t)(base + lm0) * N;
            if (live1) cr1 = C + (size_t)(base + lm1) * N;
        } else {
            live0 = lm0 < cnt;
            live1 = lm1 < cnt;
            if (live0) {
                int a = g_assign[base + lm0];
                int tok = a >> 1, slot = a & 1;
                sc0 = g_topw[tok * 2 + slot];
                cr0 = g_moe + (size_t)slot * TCOUNT * MDIM + (size_t)tok * N;
            }
            if (live1) {
                int a = g_assign[base + lm1];
                int tok = a >> 1, slot = a & 1;
                sc1 = g_topw[tok * 2 + slot];
                cr1 = g_moe + (size_t)slot * TCOUNT * MDIM + (size_t)tok * N;
            }
        }
        #pragma unroll
        for (int nt = 0; nt < 4; nt++) {
            int col = n0 + n0w + nt * 8 + qcol;
            float2 v0 = make_float2(acc[mt][nt][0], acc[mt][nt][1]);
            float2 v1 = make_float2(acc[mt][nt][2], acc[mt][nt][3]);
            if (MODE == 0 || MODE == 3) {
                float2 bv = *(const float2*)(bias + col);
                v0.x += bv.x; v0.y += bv.y;
                v1.x += bv.x; v1.y += bv.y;
                if (MODE == 0 && res) {
                    float2 r0 = *(const float2*)(rr0 + col);
                    float2 r1 = *(const float2*)(rr1 + col);
                    v0.x += r0.x; v0.y += r0.y;
                    v1.x += r1.x; v1.y += r1.y;
                }
            } else if (MODE == 2) {
                v0.x *= sc0; v0.y *= sc0;
                v1.x *= sc1; v1.y *= sc1;
            }
            if (MODE == 3) {
                *(__nv_bfloat162*)(cb0 + col) = __floats2bfloat162_rn(v0.x, v0.y);
                *(__nv_bfloat162*)(cb1 + col) = __floats2bfloat162_rn(v1.x, v1.y);
            } else {
                if (live0) *(float2*)(cr0 + col) = v0;
                if (live1) *(float2*)(cr1 + col) = v1;
            }
        }
    }
}

// ---------------- tensor-core flash attention (causal, bf16 HMMA) ------------
#define APAD 72

__global__ void __launch_bounds__(256) attn_mma(
    const __nv_bfloat16* __restrict__ qkvb,
    __nv_bfloat16* __restrict__ ctxh,
    __nv_bfloat16* __restrict__ ctxl)
{
    __shared__ __nv_bfloat16 sm[128 * APAD];

    // heavy-first: largest q-tiles (most K-tiles) launch first
    int qt = (int)gridDim.x - 1 - (int)blockIdx.x;
    int h = blockIdx.y, b = blockIdx.z;
    int tid = threadIdx.x, wid = tid >> 5, lane = tid & 31;
    int qbase = qt * 128;
    uint32_t smb = smem_u32(sm);

    {
        int r = tid >> 1, ch = (tid & 1) * 32;
        const __nv_bfloat16* src = qkvb + (size_t)(b * SLEN + qbase + r) * NQKV + h * DHEAD + ch;
        __nv_bfloat16* dst = sm + r * APAD + ch;
        *(uint4*)(dst)      = *(const uint4*)(src);
        *(uint4*)(dst + 8)  = *(const uint4*)(src + 8);
        *(uint4*)(dst + 16) = *(const uint4*)(src + 16);
        *(uint4*)(dst + 24) = *(const uint4*)(src + 24);
    }
    __syncthreads();
    uint32_t qa[4][4];
    #pragma unroll
    for (int ks = 0; ks < 4; ks++) {
        uint32_t addr = smb + (uint32_t)(((wid * 16 + (lane & 15)) * APAD
                                          + ks * 16 + (lane >> 4) * 8) * 2);
        ldsm4(qa[ks], addr);
    }
    __syncthreads();

    __nv_bfloat16* Ks = sm;
    __nv_bfloat16* Vs = sm + 64 * APAD;
    uint32_t smbK = smb;
    uint32_t smbV = smb + 64 * APAD * 2;

    float O[8][4];
    #pragma unroll
    for (int nt = 0; nt < 8; nt++)
        #pragma unroll
        for (int r = 0; r < 4; r++) O[nt][r] = 0.f;
    float m0 = -1e30f, m1 = -1e30f, l0 = 0.f, l1 = 0.f;

    int gmin = qbase + wid * 16;
    int grow0 = gmin + (lane >> 2);
    int nkt = 2 * qt + 2;

    for (int jt = 0; jt < nkt; jt++) {
        int kb = jt * 64;
        {
            int r = tid >> 2, c = (tid & 3) * 16;
            size_t trow = (size_t)(b * SLEN + kb + r) * NQKV + h * DHEAD + c;
            *(uint4*)(Ks + r * APAD + c)     = *(const uint4*)(qkvb + trow + MDIM);
            *(uint4*)(Ks + r * APAD + c + 8) = *(const uint4*)(qkvb + trow + MDIM + 8);
            *(uint4*)(Vs + r * APAD + c)     = *(const uint4*)(qkvb + trow + 2 * MDIM);
            *(uint4*)(Vs + r * APAD + c + 8) = *(const uint4*)(qkvb + trow + 2 * MDIM + 8);
        }
        __syncthreads();

        bool skip = kb > gmin + 15;
        if (!skip) {
            float S[8][4];
            #pragma unroll
            for (int nt = 0; nt < 8; nt++)
                #pragma unroll
                for (int r = 0; r < 4; r++) S[nt][r] = 0.f;
            #pragma unroll
            for (int ks = 0; ks < 4; ks++) {
                #pragma unroll
                for (int np = 0; np < 4; np++) {
                    uint32_t bb[4];
                    uint32_t addr = smbK + (uint32_t)(((np * 16 + (lane & 7)
                                      + ((lane >> 4) & 1) * 8) * APAD
                                      + ks * 16 + ((lane >> 3) & 1) * 8) * 2);
                    ldsm4(bb, addr);
                    mma_bf16(S[2 * np],     qa[ks], bb);
                    mma_bf16(S[2 * np + 1], qa[ks], bb + 2);
                }
            }
            if (kb + 63 > gmin) {
                #pragma unroll
                for (int nt = 0; nt < 8; nt++) {
                    int gc = kb + nt * 8 + (lane & 3) * 2;
                    if (gc     > grow0)     S[nt][0] = -1e30f;
                    if (gc + 1 > grow0)     S[nt][1] = -1e30f;
                    if (gc     > grow0 + 8) S[nt][2] = -1e30f;
                    if (gc + 1 > grow0 + 8) S[nt][3] = -1e30f;
                }
            }
            float tm0 = -1e30f, tm1 = -1e30f;
            #pragma unroll
            for (int nt = 0; nt < 8; nt++) {
                tm0 = fmaxf(tm0, fmaxf(S[nt][0], S[nt][1]));
                tm1 = fmaxf(tm1, fmaxf(S[nt][2], S[nt][3]));
            }
            tm0 = fmaxf(tm0, __shfl_xor_sync(0xffffffffu, tm0, 1));
            tm0 = fmaxf(tm0, __shfl_xor_sync(0xffffffffu, tm0, 2));
            tm1 = fmaxf(tm1, __shfl_xor_sync(0xffffffffu, tm1, 1));
            tm1 = fmaxf(tm1, __shfl_xor_sync(0xffffffffu, tm1, 2));
            float nm0 = fmaxf(m0, tm0), nm1 = fmaxf(m1, tm1);
            float sc0 = __expf(m0 - nm0), sc1 = __expf(m1 - nm1);
            float rs0 = 0.f, rs1 = 0.f;
            #pragma unroll
            for (int nt = 0; nt < 8; nt++) {
                S[nt][0] = __expf(S[nt][0] - nm0);
                S[nt][1] = __expf(S[nt][1] - nm0);
                S[nt][2] = __expf(S[nt][2] - nm1);
                S[nt][3] = __expf(S[nt][3] - nm1);
                rs0 += S[nt][0] + S[nt][1];
                rs1 += S[nt][2] + S[nt][3];
            }
            rs0 += __shfl_xor_sync(0xffffffffu, rs0, 1);
            rs0 += __shfl_xor_sync(0xffffffffu, rs0, 2);
            rs1 += __shfl_xor_sync(0xffffffffu, rs1, 1);
            rs1 += __shfl_xor_sync(0xffffffffu, rs1, 2);
            l0 = l0 * sc0 + rs0; l1 = l1 * sc1 + rs1;
            m0 = nm0; m1 = nm1;
            #pragma unroll
            for (int nt = 0; nt < 8; nt++) {
                O[nt][0] *= sc0; O[nt][1] *= sc0;
                O[nt][2] *= sc1; O[nt][3] *= sc1;
            }
            uint32_t pa[4][4];
            #pragma unroll
            for (int ks = 0; ks < 4; ks++) {
                pa[ks][0] = packbf(S[2 * ks][0],     S[2 * ks][1]);
                pa[ks][1] = packbf(S[2 * ks][2],     S[2 * ks][3]);
                pa[ks][2] = packbf(S[2 * ks + 1][0], S[2 * ks + 1][1]);
                pa[ks][3] = packbf(S[2 * ks + 1][2], S[2 * ks + 1][3]);
            }
            #pragma unroll
            for (int ks = 0; ks < 4; ks++) {
                #pragma unroll
                for (int np = 0; np < 4; np++) {
                    uint32_t bv[4];
                    uint32_t addr = smbV + (uint32_t)(((ks * 16 + (lane & 15)) * APAD
                                      + np * 16 + (lane >> 4) * 8) * 2);
                    ldsm4t(bv, addr);
                    mma_bf16(O[2 * np],     pa[ks], bv);
                    mma_bf16(O[2 * np + 1], pa[ks], bv + 2);
                }
            }
        }
        __syncthreads();
    }

    float inv0 = 1.f / l0, inv1 = 1.f / l1;
    size_t tok0 = (size_t)(b * SLEN + qbase + wid * 16 + (lane >> 2));
    #pragma unroll
    for (int nt = 0; nt < 8; nt++) {
        int col = h * DHEAD + nt * 8 + (lane & 3) * 2;
        float v0 = O[nt][0] * inv0, v1 = O[nt][1] * inv0;
        float v2 = O[nt][2] * inv1, v3 = O[nt][3] * inv1;
        __nv_bfloat16 h0, h1, h2, h3, q0, q1, q2, q3;
        split_bf16(v0, h0, q0); split_bf16(v1, h1, q1);
        split_bf16(v2, h2, q2); split_bf16(v3, h3, q3);
        __nv_bfloat162 ph0 = {h0, h1}, pl0 = {q0, q1};
        __nv_bfloat162 ph1 = {h2, h3}, pl1 = {q2, q3};
        *(__nv_bfloat162*)(ctxh + tok0 * MDIM + col)       = ph0;
        *(__nv_bfloat162*)(ctxl + tok0 * MDIM + col)       = pl0;
        *(__nv_bfloat162*)(ctxh + (tok0 + 8) * MDIM + col) = ph1;
        *(__nv_bfloat162*)(ctxl + (tok0 + 8) * MDIM + col) = pl1;
    }
}

// ---------------- routing ----------------------------------------------------
__global__ void route_kernel(const float* __restrict__ h2,
                             const float* __restrict__ gw) {
    int t = blockIdx.x * 8 + (threadIdx.x >> 5);
    int lane = threadIdx.x & 31;
    if (t >= TCOUNT) return;
    const float* hr = h2 + (size_t)t * MDIM;
    float acc[NEXP];
    #pragma unroll
    for (int e = 0; e < NEXP; e++) acc[e] = 0.f;
    for (int i = lane; i < MDIM; i += 32) {
        float hv = hr[i];
        #pragma unroll
        for (int e = 0; e < NEXP; e++) acc[e] += hv * gw[e * MDIM + i];
    }
    #pragma unroll
    for (int e = 0; e < NEXP; e++) acc[e] = warp_sum(acc[e]);
    if (lane == 0) {
        float mx = acc[0];
        #pragma unroll
        for (int e = 1; e < NEXP; e++) mx = fmaxf(mx, acc[e]);
        float ex[NEXP];
        #pragma unroll
        for (int e = 0; e < NEXP; e++) ex[e] = __expf(acc[e] - mx);
        int i0 = 0;
        #pragma unroll
        for (int e = 1; e < NEXP; e++) if (acc[e] > acc[i0]) i0 = e;
        int i1 = (i0 == 0) ? 1 : 0;
        #pragma unroll
        for (int e = 0; e < NEXP; e++)
            if (e != i0 && acc[e] > acc[i1]) i1 = e;
        float denom = 1.f / (ex[i0] + ex[i1]);
        g_topi[t * 2 + 0] = i0;
        g_topi[t * 2 + 1] = i1;
        g_topw[t * 2 + 0] = ex[i0] * denom;
        g_topw[t * 2 + 1] = ex[i1] * denom;
        atomicAdd(&g_cnt[i0], 1);
        atomicAdd(&g_cnt[i1], 1);
    }
}

__global__ void prefix_kernel() {
    if (threadIdx.x == 0 && blockIdx.x == 0) {
        int acc = 0;
        for (int e = 0; e < NEXP; e++) {
            g_base[e] = acc;
            acc += g_cnt[e];
            g_fill[e] = 0;
        }
    }
}

__global__ void assign_kernel() {
    int t = blockIdx.x * blockDim.x + threadIdx.x;
    if (t < TCOUNT) {
        #pragma unroll
        for (int s = 0; s < 2; s++) {
            int e = g_topi[t * 2 + s];
            int pos = g_base[e] + atomicAdd(&g_fill[e], 1);
            g_assign[pos] = t * 2 + s;
        }
    }
}

// ---------------- elementwise -------------------------------------------------
__global__ void silu_mul_kernel(const float* __restrict__ u,
                                const float* __restrict__ g3,
                                __nv_bfloat16* __restrict__ acth,
                                __nv_bfloat16* __restrict__ actl, int n) {
    for (int i = blockIdx.x * blockDim.x + threadIdx.x; i < n;
         i += gridDim.x * blockDim.x) {
        float a = u[i];
        float s = a / (1.f + __expf(-a));
        float v = s * g3[i];
        __nv_bfloat16 h, l;
        split_bf16(v, h, l);
        acth[i] = h;
        actl[i] = l;
    }
}

__global__ void final_add_kernel(const float* __restrict__ y,
                                 float* __restrict__ out, int n) {
    for (int i = blockIdx.x * blockDim.x + threadIdx.x; i < n;
         i += gridDim.x * blockDim.x) {
        out[i] = y[i] + g_moe[i] + g_moe[(size_t)TCOUNT * MDIM + i];
    }
}

// ---------------- launch ------------------------------------------------------
extern "C" void kernel_launch(void* const* d_in, const int* in_sizes, int n_in,
                              void* d_out, int out_size) {
    const float* x     = (const float*)d_in[0];
    const float* ln1g  = (const float*)d_in[1];
    const float* ln1b  = (const float*)d_in[2];
    const float* qkvw  = (const float*)d_in[3];
    const float* qkvb  = (const float*)d_in[4];
    const float* ow    = (const float*)d_in[5];
    const float* ob    = (const float*)d_in[6];
    const float* ln2g  = (const float*)d_in[7];
    const float* ln2b  = (const float*)d_in[8];
    const float* gatew = (const float*)d_in[9];
    const float* w1    = (const float*)d_in[10];
    const float* w2    = (const float*)d_in[11];
    const float* w3    = (const float*)d_in[12];
    float* out = (float*)d_out;

    cudaFuncSetAttribute(hmma_gemm<0>,
                         cudaFuncAttributeMaxDynamicSharedMemorySize, GSMEM_B);
    cudaFuncSetAttribute(hmma_gemm<1>,
                         cudaFuncAttributeMaxDynamicSharedMemorySize, GSMEM_B);
    cudaFuncSetAttribute(hmma_gemm<2>,
                         cudaFuncAttributeMaxDynamicSharedMemorySize, GSMEM_B);
    cudaFuncSetAttribute(hmma_gemm<3>,
                         cudaFuncAttributeMaxDynamicSharedMemorySize, GSMEM_B);

    void *hh, *hl, *ctxh, *ctxl, *h2h, *h2l, *acth, *actl, *qkvbp;
    void *qwh, *qwl, *owh, *owl, *w1h, *w1l, *w3h, *w3l, *w2h, *w2l;
    cudaGetSymbolAddress(&hh, g_hh);     cudaGetSymbolAddress(&hl, g_hl);
    cudaGetSymbolAddress(&ctxh, g_ctxh); cudaGetSymbolAddress(&ctxl, g_ctxl);
    cudaGetSymbolAddress(&h2h, g_h2h);   cudaGetSymbolAddress(&h2l, g_h2l);
    cudaGetSymbolAddress(&acth, g_acth); cudaGetSymbolAddress(&actl, g_actl);
    cudaGetSymbolAddress(&qkvbp, g_qkvb);
    cudaGetSymbolAddress(&qwh, g_qkvwh); cudaGetSymbolAddress(&qwl, g_qkvwl);
    cudaGetSymbolAddress(&owh, g_owh);   cudaGetSymbolAddress(&owl, g_owl);
    cudaGetSymbolAddress(&w1h, g_w1h);   cudaGetSymbolAddress(&w1l, g_w1l);
    cudaGetSymbolAddress(&w3h, g_w3h);   cudaGetSymbolAddress(&w3l, g_w3l);
    cudaGetSymbolAddress(&w2h, g_w2h);   cudaGetSymbolAddress(&w2l, g_w2l);
    void *yp, *h2p, *up, *g3p;
    cudaGetSymbolAddress(&yp, g_y);
    cudaGetSymbolAddress(&h2p, g_h2);
    cudaGetSymbolAddress(&up, g_u);
    cudaGetSymbolAddress(&g3p, g_g3);

    // (0) zero counters
    zero_cnt_kernel<<<1, 32>>>();
    // (1) all weight conversions in one launch
    cvt_all_kernel<<<8192, 256>>>(qkvw, ow, w1, w3, w2);
    // (2) h = LN1(x) -> bf16 hi/lo
    ln_kernel<<<TCOUNT, 256>>>(x, ln1g, ln1b, nullptr,
                               (__nv_bfloat16*)hh, (__nv_bfloat16*)hl);
    // (3) qkv = h @ qkvw^T + qkvb -> bf16 directly
    hmma_gemm<3><<<dim3(NQKV / 128, TCOUNT / 128), 256, GSMEM_B>>>(
        (__nv_bfloat16*)hh, (__nv_bfloat16*)hl,
        (__nv_bfloat16*)qwh, (__nv_bfloat16*)qwl,
        qkvb, nullptr, (float*)qkvbp, NQKV, MDIM);
    // (4) tensor-core causal flash attention -> ctx hi/lo
    attn_mma<<<dim3(SLEN / 128, NHEAD, BATCH), 256>>>(
        (__nv_bfloat16*)qkvbp, (__nv_bfloat16*)ctxh, (__nv_bfloat16*)ctxl);
    // (5) y = x + ctx @ ow^T + ob
    hmma_gemm<0><<<dim3(MDIM / 128, TCOUNT / 128), 256, GSMEM_B>>>(
        (__nv_bfloat16*)ctxh, (__nv_bfloat16*)ctxl,
        (__nv_bfloat16*)owh, (__nv_bfloat16*)owl,
        ob, x, (float*)yp, MDIM, MDIM);
    // (6) h2 = LN2(y) -> fp32 + bf16 hi/lo
    ln_kernel<<<TCOUNT, 256>>>((float*)yp, ln2g, ln2b, (float*)h2p,
                               (__nv_bfloat16*)h2h, (__nv_bfloat16*)h2l);
    // (7-9) routing
    route_kernel<<<TCOUNT / 8, 256>>>((float*)h2p, gatew);
    prefix_kernel<<<1, 32>>>();
    assign_kernel<<<TCOUNT / 256, 256>>>();
    // (10,11) u = h2g @ w1^T ; g3 = h2g @ w3^T
    hmma_gemm<1><<<dim3(DFFN / 128, NASSIGN / 128, NEXP), 256, GSMEM_B>>>(
        (__nv_bfloat16*)h2h, (__nv_bfloat16*)h2l,
        (__nv_bfloat16*)w1h, (__nv_bfloat16*)w1l,
        nullptr, nullptr, (float*)up, DFFN, MDIM);
    hmma_gemm<1><<<dim3(DFFN / 128, NASSIGN / 128, NEXP), 256, GSMEM_B>>>(
        (__nv_bfloat16*)h2h, (__nv_bfloat16*)h2l,
        (__nv_bfloat16*)w3h, (__nv_bfloat16*)w3l,
        nullptr, nullptr, (float*)g3p, DFFN, MDIM);
    // (12) act = silu(u) * g3 -> bf16 hi/lo
    silu_mul_kernel<<<4096, 256>>>((float*)up, (float*)g3p,
                                   (__nv_bfloat16*)acth, (__nv_bfloat16*)actl,
                                   NASSIGN * DFFN);
    // (13) moe scatter: w * (act @ w2^T)
    hmma_gemm<2><<<dim3(MDIM / 128, NASSIGN / 128, NEXP), 256, GSMEM_B>>>(
        (__nv_bfloat16*)acth, (__nv_bfloat16*)actl,
        (__nv_bfloat16*)w2h, (__nv_bfloat16*)w2l,
        nullptr, nullptr, nullptr, MDIM, DFFN);
    // (14) out = y + moe0 + moe1
    final_add_kernel<<<4096, 256>>>((float*)yp, out, TCOUNT * MDIM);
}

// round 17
// speedup vs baseline: 2.2203x; 1.9227x over previous
#include <cuda_runtime.h>
#include <cuda_fp16.h>
#include <math.h>
#include <stdint.h>

// Problem constants
#define BATCH 2
#define SLEN  2048
#define TCOUNT 4096      // BATCH*SLEN
#define MDIM  1024
#define NHEAD 16
#define DHEAD 64
#define NQKV  3072
#define DFFN  4096
#define NEXP  8
#define NASSIGN 8192     // TCOUNT * TOP_K

// ---------------- scratch (static device globals; no runtime alloc) ----------
__device__ float g_y   [TCOUNT * MDIM];
__device__ float g_h2  [TCOUNT * MDIM];
__device__ float g_u   [NASSIGN * DFFN];
__device__ float g_g3  [NASSIGN * DFFN];
__device__ float g_moe [2 * TCOUNT * MDIM];
__device__ float g_topw[TCOUNT * 2];
__device__ int   g_topi[TCOUNT * 2];
__device__ int   g_cnt [NEXP];
__device__ int   g_base[NEXP];
__device__ int   g_fill[NEXP];
__device__ int   g_assign[NASSIGN];

// fp16 buffers
__device__ __half g_qkv16[TCOUNT * NQKV];
__device__ __half g_h16  [TCOUNT * MDIM];
__device__ __half g_ctx16[TCOUNT * MDIM];
__device__ __half g_h216 [TCOUNT * MDIM];
__device__ __half g_act16[NASSIGN * DFFN];
__device__ __half g_qkvw16[NQKV * MDIM];
__device__ __half g_ow16[MDIM * MDIM];
__device__ __half g_w116[NEXP * DFFN * MDIM];
__device__ __half g_w316[NEXP * DFFN * MDIM];
__device__ __half g_w216[NEXP * MDIM * DFFN];

// ---------------- helpers ----------------------------------------------------
__device__ __forceinline__ float warp_sum(float v) {
    #pragma unroll
    for (int o = 16; o; o >>= 1) v += __shfl_xor_sync(0xffffffffu, v, o);
    return v;
}
__device__ __forceinline__ uint32_t smem_u32(const void* p) {
    return (uint32_t)__cvta_generic_to_shared(p);
}
__device__ __forceinline__ uint32_t packh(float a, float b) {
    __half2 t = __floats2half2_rn(a, b);
    return *reinterpret_cast<uint32_t*>(&t);
}
__device__ __forceinline__ void ldsm4(uint32_t* r, uint32_t addr) {
    asm volatile("ldmatrix.sync.aligned.m8n8.x4.shared.b16 {%0,%1,%2,%3}, [%4];"
                 : "=r"(r[0]), "=r"(r[1]), "=r"(r[2]), "=r"(r[3]) : "r"(addr));
}
__device__ __forceinline__ void ldsm4t(uint32_t* r, uint32_t addr) {
    asm volatile("ldmatrix.sync.aligned.m8n8.x4.trans.shared.b16 {%0,%1,%2,%3}, [%4];"
                 : "=r"(r[0]), "=r"(r[1]), "=r"(r[2]), "=r"(r[3]) : "r"(addr));
}
__device__ __forceinline__ void mma_f16(float* d, const uint32_t* a, const uint32_t* b) {
    asm volatile(
        "mma.sync.aligned.m16n8k16.row.col.f32.f16.f16.f32 "
        "{%0,%1,%2,%3}, {%4,%5,%6,%7}, {%8,%9}, {%0,%1,%2,%3};"
        : "+f"(d[0]), "+f"(d[1]), "+f"(d[2]), "+f"(d[3])
        : "r"(a[0]), "r"(a[1]), "r"(a[2]), "r"(a[3]), "r"(b[0]), "r"(b[1]));
}
__device__ __forceinline__ void cp16(uint32_t dst, const void* src) {
    asm volatile("cp.async.cg.shared.global [%0], [%1], 16;" :: "r"(dst), "l"(src));
}
#define CP_COMMIT() asm volatile("cp.async.commit_group;" ::: "memory")
#define CP_WAIT2()  asm volatile("cp.async.wait_group 2;" ::: "memory")
#define CP_WAIT1()  asm volatile("cp.async.wait_group 1;" ::: "memory")
#define CP_WAIT0()  asm volatile("cp.async.wait_group 0;" ::: "memory")

// tile geometry: CHUNK 32, stride 40 (80 B rows), fp16 single precision term.
// 2 tiles per stage (A,B), 3 stages -> 61.4 KB smem, 2 CTAs/SM.
#define CHUNK 32
#define TPAD 40
#define TILE_ELT (128 * TPAD)          // 5120 halves
#define TILE_B   (TILE_ELT * 2)        // 10240 B
#define STAGE_B  (2 * TILE_B)          // 20480 B
#define NSTAGE   3
#define GSMEM_B  (NSTAGE * STAGE_B)    // 61440 B
#define ROW_B    (TPAD * 2)            // 80 B

__device__ __forceinline__ void stage_tile(uint32_t d, const __half* s) {
    cp16(d, s); cp16(d + 16, s + 8);
}

// ---------------- init --------------------------------------------------------
__global__ void zero_cnt_kernel() {
    if (threadIdx.x < NEXP) g_cnt[threadIdx.x] = 0;
}

// ---------------- merged weight conversion (fp32 -> fp16) ---------------------
__device__ __forceinline__ void cvt_seg(const float* __restrict__ src,
                                        __half* __restrict__ dst, int n,
                                        int gtid, int gstride) {
    for (int i = gtid * 4; i < n; i += gstride) {
        float4 v = *(const float4*)(src + i);
        __half2 a = __floats2half2_rn(v.x, v.y);
        __half2 b = __floats2half2_rn(v.z, v.w);
        *(__half2*)(dst + i)     = a;
        *(__half2*)(dst + i + 2) = b;
    }
}

__global__ void cvt_all_kernel(const float* qkvw, const float* ow,
                               const float* w1, const float* w3, const float* w2) {
    int gtid = blockIdx.x * blockDim.x + threadIdx.x;
    int gstride = gridDim.x * blockDim.x * 4;
    cvt_seg(qkvw, g_qkvw16, NQKV * MDIM, gtid, gstride);
    cvt_seg(ow,   g_ow16,   MDIM * MDIM, gtid, gstride);
    cvt_seg(w1,   g_w116,   NEXP * DFFN * MDIM, gtid, gstride);
    cvt_seg(w3,   g_w316,   NEXP * DFFN * MDIM, gtid, gstride);
    cvt_seg(w2,   g_w216,   NEXP * MDIM * DFFN, gtid, gstride);
}

// ---------------- LayerNorm ---------------------------------------------------
__global__ void ln_kernel(const float* __restrict__ x,
                          const float* __restrict__ g,
                          const float* __restrict__ b,
                          float* __restrict__ outf,
                          __half* __restrict__ outh) {
    int t = blockIdx.x;
    const float* xr = x + (size_t)t * MDIM;
    int tid = threadIdx.x;
    float v[4];
    float s = 0.f, s2 = 0.f;
    #pragma unroll
    for (int i = 0; i < 4; i++) {
        v[i] = xr[tid + 256 * i];
        s += v[i];
        s2 += v[i] * v[i];
    }
    __shared__ float rs[8], rs2[8];
    s = warp_sum(s); s2 = warp_sum(s2);
    if ((tid & 31) == 0) { rs[tid >> 5] = s; rs2[tid >> 5] = s2; }
    __syncthreads();
    if (tid < 32) {
        float a = (tid < 8) ? rs[tid] : 0.f;
        float a2 = (tid < 8) ? rs2[tid] : 0.f;
        a = warp_sum(a); a2 = warp_sum(a2);
        if (tid == 0) { rs[0] = a; rs2[0] = a2; }
    }
    __syncthreads();
    float mean = rs[0] * (1.f / MDIM);
    float var  = rs2[0] * (1.f / MDIM) - mean * mean;
    float inv  = rsqrtf(var + 1e-5f);
    size_t ro = (size_t)t * MDIM;
    #pragma unroll
    for (int i = 0; i < 4; i++) {
        int c = tid + 256 * i;
        float o = (v[i] - mean) * inv * g[c] + b[c];
        if (outf) outf[ro + c] = o;
        outh[ro + c] = __float2half_rn(o);
    }
}

// ---------------- pipelined fp16 HMMA GEMM -----------------------------------
// MODE 0: +bias, optional +res, fp32 out.
// MODE 1: gather A rows via g_assign, fp32 out.
// MODE 2: A = act rows (base+row), scaled scatter to g_moe.
// MODE 3: +bias, fp16 out (C reinterpreted as __half*).
template<int MODE>
__global__ void __launch_bounds__(256, 2) hmma_gemm(
    const __half* __restrict__ A_, const __half* __restrict__ W_,
    const float* __restrict__ bias, const float* __restrict__ res,
    float* __restrict__ C, int N, int K)
{
    extern __shared__ __half sm[];

    int e = (MODE == 1 || MODE == 2) ? blockIdx.z : 0;
    int cnt = TCOUNT, base = 0;
    if (MODE == 1 || MODE == 2) { cnt = g_cnt[e]; base = g_base[e]; }
    int m0 = blockIdx.y * 128;
    if ((MODE == 1 || MODE == 2) && m0 >= cnt) return;
    int n0 = blockIdx.x * 128;

    const __half* Wp = W_;
    if (MODE == 1) Wp += (size_t)e * DFFN * MDIM;
    if (MODE == 2) Wp += (size_t)e * MDIM * DFFN;

    int tid = threadIdx.x;
    int wid = tid >> 5;
    int lane = tid & 31;
    int m0w = (wid & 1) * 64;
    int n0w = (wid >> 1) * 32;

    int crow = tid >> 1;
    int coff = (tid & 1) * 16;
    const __half* a_src;
    if (MODE == 0 || MODE == 3) {
        a_src = A_ + (size_t)(m0 + crow) * K + coff;
    } else if (MODE == 1) {
        int lr = m0 + crow; if (lr >= cnt) lr = cnt - 1;
        int tok = g_assign[base + lr] >> 1;
        a_src = A_ + (size_t)tok * K + coff;
    } else {
        int lr = m0 + crow; if (lr >= cnt) lr = cnt - 1;
        a_src = A_ + (size_t)(base + lr) * K + coff;
    }
    const __half* b_src = Wp + (size_t)(n0 + crow) * K + coff;

    uint32_t smb = smem_u32(sm);
    uint32_t ldst = smb + (uint32_t)((crow * TPAD + coff) * 2);

    uint32_t laneA = (uint32_t)(((m0w + (lane & 15)) * TPAD + ((lane >> 4) * 8)) * 2);
    uint32_t laneB = (uint32_t)(((n0w + (lane & 7) + ((lane >> 4) & 1) * 8) * TPAD
                                 + ((lane >> 3) & 1) * 8) * 2);

    float acc[4][4][4];
    #pragma unroll
    for (int i = 0; i < 4; i++)
        #pragma unroll
        for (int j = 0; j < 4; j++)
            #pragma unroll
            for (int r = 0; r < 4; r++) acc[i][j][r] = 0.f;

    int nch = K >> 5;

    #pragma unroll
    for (int s = 0; s < NSTAGE; s++) {
        int kc = s * CHUNK;
        uint32_t d = ldst + (uint32_t)(s * STAGE_B);
        stage_tile(d, a_src + kc);
        stage_tile(d + TILE_B, b_src + kc);
        CP_COMMIT();
    }

    int stg = 0;
    for (int c = 0; c < nch; c++) {
        int rem = nch - 1 - c;
        if (rem >= 2) CP_WAIT2(); else if (rem == 1) CP_WAIT1(); else CP_WAIT0();
        __syncthreads();

        uint32_t sb = smb + (uint32_t)(stg * STAGE_B);
        uint32_t aA = sb + laneA;
        uint32_t bB = sb + TILE_B + laneB;

        #pragma unroll
        for (int ks = 0; ks < 2; ks++) {
            uint32_t koff = (uint32_t)(ks * 32);
            uint32_t bf[4][2];
            ldsm4(&bf[0][0], bB + koff);
            ldsm4(&bf[2][0], bB + 16 * ROW_B + koff);
            #pragma unroll
            for (int mt = 0; mt < 4; mt++) {
                uint32_t af[4];
                ldsm4(af, aA + (uint32_t)(mt * 16 * ROW_B) + koff);
                #pragma unroll
                for (int nt = 0; nt < 4; nt++) mma_f16(acc[mt][nt], af, bf[nt]);
            }
        }
        __syncthreads();

        int cn = c + NSTAGE;
        if (cn < nch) {
            int kc = cn * CHUNK;
            uint32_t d = ldst + (uint32_t)(stg * STAGE_B);
            stage_tile(d, a_src + kc);
            stage_tile(d + TILE_B, b_src + kc);
            CP_COMMIT();
        }
        stg = (stg + 1 == NSTAGE) ? 0 : stg + 1;
    }

    int qrow = lane >> 2;
    int qcol = (lane & 3) * 2;
    #pragma unroll
    for (int mt = 0; mt < 4; mt++) {
        int lm0 = m0 + m0w + mt * 16 + qrow;
        int lm1 = lm0 + 8;
        const float* rr0 = nullptr; const float* rr1 = nullptr;
        float* cr0 = nullptr; float* cr1 = nullptr;
        __half* cb0 = nullptr; __half* cb1 = nullptr;
        float sc0 = 1.f, sc1 = 1.f;
        bool live0 = true, live1 = true;
        if (MODE == 0) {
            cr0 = C + (size_t)lm0 * N;
            cr1 = C + (size_t)lm1 * N;
            if (res) { rr0 = res + (size_t)lm0 * N; rr1 = res + (size_t)lm1 * N; }
        } else if (MODE == 3) {
            cb0 = (__half*)C + (size_t)lm0 * N;
            cb1 = (__half*)C + (size_t)lm1 * N;
        } else if (MODE == 1) {
            live0 = lm0 < cnt;
            live1 = lm1 < cnt;
            if (live0) cr0 = C + (size_t)(base + lm0) * N;
            if (live1) cr1 = C + (size_t)(base + lm1) * N;
        } else {
            live0 = lm0 < cnt;
            live1 = lm1 < cnt;
            if (live0) {
                int a = g_assign[base + lm0];
                int tok = a >> 1, slot = a & 1;
                sc0 = g_topw[tok * 2 + slot];
                cr0 = g_moe + (size_t)slot * TCOUNT * MDIM + (size_t)tok * N;
            }
            if (live1) {
                int a = g_assign[base + lm1];
                int tok = a >> 1, slot = a & 1;
                sc1 = g_topw[tok * 2 + slot];
                cr1 = g_moe + (size_t)slot * TCOUNT * MDIM + (size_t)tok * N;
            }
        }
        #pragma unroll
        for (int nt = 0; nt < 4; nt++) {
            int col = n0 + n0w + nt * 8 + qcol;
            float2 v0 = make_float2(acc[mt][nt][0], acc[mt][nt][1]);
            float2 v1 = make_float2(acc[mt][nt][2], acc[mt][nt][3]);
            if (MODE == 0 || MODE == 3) {
                float2 bv = *(const float2*)(bias + col);
                v0.x += bv.x; v0.y += bv.y;
                v1.x += bv.x; v1.y += bv.y;
                if (MODE == 0 && res) {
                    float2 r0 = *(const float2*)(rr0 + col);
                    float2 r1 = *(const float2*)(rr1 + col);
                    v0.x += r0.x; v0.y += r0.y;
                    v1.x += r1.x; v1.y += r1.y;
                }
            } else if (MODE == 2) {
                v0.x *= sc0; v0.y *= sc0;
                v1.x *= sc1; v1.y *= sc1;
            }
            if (MODE == 3) {
                *(__half2*)(cb0 + col) = __floats2half2_rn(v0.x, v0.y);
                *(__half2*)(cb1 + col) = __floats2half2_rn(v1.x, v1.y);
            } else {
                if (live0) *(float2*)(cr0 + col) = v0;
                if (live1) *(float2*)(cr1 + col) = v1;
            }
        }
    }
}

// ---------------- tensor-core flash attention (causal, fp16 HMMA) ------------
#define APAD 72

__global__ void __launch_bounds__(256) attn_mma(
    const __half* __restrict__ qkvb,
    __half* __restrict__ ctx16)
{
    __shared__ __half sm[128 * APAD];

    // heavy-first: largest q-tiles launch first
    int qt = (int)gridDim.x - 1 - (int)blockIdx.x;
    int h = blockIdx.y, b = blockIdx.z;
    int tid = threadIdx.x, wid = tid >> 5, lane = tid & 31;
    int qbase = qt * 128;
    uint32_t smb = smem_u32(sm);

    {
        int r = tid >> 1, ch = (tid & 1) * 32;
        const __half* src = qkvb + (size_t)(b * SLEN + qbase + r) * NQKV + h * DHEAD + ch;
        __half* dst = sm + r * APAD + ch;
        *(uint4*)(dst)      = *(const uint4*)(src);
        *(uint4*)(dst + 8)  = *(const uint4*)(src + 8);
        *(uint4*)(dst + 16) = *(const uint4*)(src + 16);
        *(uint4*)(dst + 24) = *(const uint4*)(src + 24);
    }
    __syncthreads();
    uint32_t qa[4][4];
    #pragma unroll
    for (int ks = 0; ks < 4; ks++) {
        uint32_t addr = smb + (uint32_t)(((wid * 16 + (lane & 15)) * APAD
                                          + ks * 16 + (lane >> 4) * 8) * 2);
        ldsm4(qa[ks], addr);
    }
    __syncthreads();

    __half* Ks = sm;
    __half* Vs = sm + 64 * APAD;
    uint32_t smbK = smb;
    uint32_t smbV = smb + 64 * APAD * 2;

    float O[8][4];
    #pragma unroll
    for (int nt = 0; nt < 8; nt++)
        #pragma unroll
        for (int r = 0; r < 4; r++) O[nt][r] = 0.f;
    float m0 = -1e30f, m1 = -1e30f, l0 = 0.f, l1 = 0.f;

    int gmin = qbase + wid * 16;
    int grow0 = gmin + (lane >> 2);
    int nkt = 2 * qt + 2;

    for (int jt = 0; jt < nkt; jt++) {
        int kb = jt * 64;
        {
            int r = tid >> 2, c = (tid & 3) * 16;
            size_t trow = (size_t)(b * SLEN + kb + r) * NQKV + h * DHEAD + c;
            *(uint4*)(Ks + r * APAD + c)     = *(const uint4*)(qkvb + trow + MDIM);
            *(uint4*)(Ks + r * APAD + c + 8) = *(const uint4*)(qkvb + trow + MDIM + 8);
            *(uint4*)(Vs + r * APAD + c)     = *(const uint4*)(qkvb + trow + 2 * MDIM);
            *(uint4*)(Vs + r * APAD + c + 8) = *(const uint4*)(qkvb + trow + 2 * MDIM + 8);
        }
        __syncthreads();

        bool skip = kb > gmin + 15;
        if (!skip) {
            float S[8][4];
            #pragma unroll
            for (int nt = 0; nt < 8; nt++)
                #pragma unroll
                for (int r = 0; r < 4; r++) S[nt][r] = 0.f;
            #pragma unroll
            for (int ks = 0; ks < 4; ks++) {
                #pragma unroll
                for (int np = 0; np < 4; np++) {
                    uint32_t bb[4];
                    uint32_t addr = smbK + (uint32_t)(((np * 16 + (lane & 7)
                                      + ((lane >> 4) & 1) * 8) * APAD
                                      + ks * 16 + ((lane >> 3) & 1) * 8) * 2);
                    ldsm4(bb, addr);
                    mma_f16(S[2 * np],     qa[ks], bb);
                    mma_f16(S[2 * np + 1], qa[ks], bb + 2);
                }
            }
            if (kb + 63 > gmin) {
                #pragma unroll
                for (int nt = 0; nt < 8; nt++) {
                    int gc = kb + nt * 8 + (lane & 3) * 2;
                    if (gc     > grow0)     S[nt][0] = -1e30f;
                    if (gc + 1 > grow0)     S[nt][1] = -1e30f;
                    if (gc     > grow0 + 8) S[nt][2] = -1e30f;
                    if (gc + 1 > grow0 + 8) S[nt][3] = -1e30f;
                }
            }
            float tm0 = -1e30f, tm1 = -1e30f;
            #pragma unroll
            for (int nt = 0; nt < 8; nt++) {
                tm0 = fmaxf(tm0, fmaxf(S[nt][0], S[nt][1]));
                tm1 = fmaxf(tm1, fmaxf(S[nt][2], S[nt][3]));
            }
            tm0 = fmaxf(tm0, __shfl_xor_sync(0xffffffffu, tm0, 1));
            tm0 = fmaxf(tm0, __shfl_xor_sync(0xffffffffu, tm0, 2));
            tm1 = fmaxf(tm1, __shfl_xor_sync(0xffffffffu, tm1, 1));
            tm1 = fmaxf(tm1, __shfl_xor_sync(0xffffffffu, tm1, 2));
            float nm0 = fmaxf(m0, tm0), nm1 = fmaxf(m1, tm1);
            float sc0 = __expf(m0 - nm0), sc1 = __expf(m1 - nm1);
            float rs0 = 0.f, rs1 = 0.f;
            #pragma unroll
            for (int nt = 0; nt < 8; nt++) {
                S[nt][0] = __expf(S[nt][0] - nm0);
                S[nt][1] = __expf(S[nt][1] - nm0);
                S[nt][2] = __expf(S[nt][2] - nm1);
                S[nt][3] = __expf(S[nt][3] - nm1);
                rs0 += S[nt][0] + S[nt][1];
                rs1 += S[nt][2] + S[nt][3];
            }
            rs0 += __shfl_xor_sync(0xffffffffu, rs0, 1);
            rs0 += __shfl_xor_sync(0xffffffffu, rs0, 2);
            rs1 += __shfl_xor_sync(0xffffffffu, rs1, 1);
            rs1 += __shfl_xor_sync(0xffffffffu, rs1, 2);
            l0 = l0 * sc0 + rs0; l1 = l1 * sc1 + rs1;
            m0 = nm0; m1 = nm1;
            #pragma unroll
            for (int nt = 0; nt < 8; nt++) {
                O[nt][0] *= sc0; O[nt][1] *= sc0;
                O[nt][2] *= sc1; O[nt][3] *= sc1;
            }
            uint32_t pa[4][4];
            #pragma unroll
            for (int ks = 0; ks < 4; ks++) {
                pa[ks][0] = packh(S[2 * ks][0],     S[2 * ks][1]);
                pa[ks][1] = packh(S[2 * ks][2],     S[2 * ks][3]);
                pa[ks][2] = packh(S[2 * ks + 1][0], S[2 * ks + 1][1]);
                pa[ks][3] = packh(S[2 * ks + 1][2], S[2 * ks + 1][3]);
            }
            #pragma unroll
            for (int ks = 0; ks < 4; ks++) {
                #pragma unroll
                for (int np = 0; np < 4; np++) {
                    uint32_t bv[4];
                    uint32_t addr = smbV + (uint32_t)(((ks * 16 + (lane & 15)) * APAD
                                      + np * 16 + (lane >> 4) * 8) * 2);
                    ldsm4t(bv, addr);
                    mma_f16(O[2 * np],     pa[ks], bv);
                    mma_f16(O[2 * np + 1], pa[ks], bv + 2);
                }
            }
        }
        __syncthreads();
    }

    float inv0 = 1.f / l0, inv1 = 1.f / l1;
    size_t tok0 = (size_t)(b * SLEN + qbase + wid * 16 + (lane >> 2));
    #pragma unroll
    for (int nt = 0; nt < 8; nt++) {
        int col = h * DHEAD + nt * 8 + (lane & 3) * 2;
        *(__half2*)(ctx16 + tok0 * MDIM + col) =
            __floats2half2_rn(O[nt][0] * inv0, O[nt][1] * inv0);
        *(__half2*)(ctx16 + (tok0 + 8) * MDIM + col) =
            __floats2half2_rn(O[nt][2] * inv1, O[nt][3] * inv1);
    }
}

// ---------------- routing ----------------------------------------------------
__global__ void route_kernel(const float* __restrict__ h2,
                             const float* __restrict__ gw) {
    int t = blockIdx.x * 8 + (threadIdx.x >> 5);
    int lane = threadIdx.x & 31;
    if (t >= TCOUNT) return;
    const float* hr = h2 + (size_t)t * MDIM;
    float acc[NEXP];
    #pragma unroll
    for (int e = 0; e < NEXP; e++) acc[e] = 0.f;
    for (int i = lane; i < MDIM; i += 32) {
        float hv = hr[i];
        #pragma unroll
        for (int e = 0; e < NEXP; e++) acc[e] += hv * gw[e * MDIM + i];
    }
    #pragma unroll
    for (int e = 0; e < NEXP; e++) acc[e] = warp_sum(acc[e]);
    if (lane == 0) {
        float mx = acc[0];
        #pragma unroll
        for (int e = 1; e < NEXP; e++) mx = fmaxf(mx, acc[e]);
        float ex[NEXP];
        #pragma unroll
        for (int e = 0; e < NEXP; e++) ex[e] = __expf(acc[e] - mx);
        int i0 = 0;
        #pragma unroll
        for (int e = 1; e < NEXP; e++) if (acc[e] > acc[i0]) i0 = e;
        int i1 = (i0 == 0) ? 1 : 0;
        #pragma unroll
        for (int e = 0; e < NEXP; e++)
            if (e != i0 && acc[e] > acc[i1]) i1 = e;
        float denom = 1.f / (ex[i0] + ex[i1]);
        g_topi[t * 2 + 0] = i0;
        g_topi[t * 2 + 1] = i1;
        g_topw[t * 2 + 0] = ex[i0] * denom;
        g_topw[t * 2 + 1] = ex[i1] * denom;
        atomicAdd(&g_cnt[i0], 1);
        atomicAdd(&g_cnt[i1], 1);
    }
}

__global__ void prefix_kernel() {
    if (threadIdx.x == 0 && blockIdx.x == 0) {
        int acc = 0;
        for (int e = 0; e < NEXP; e++) {
            g_base[e] = acc;
            acc += g_cnt[e];
            g_fill[e] = 0;
        }
    }
}

__global__ void assign_kernel() {
    int t = blockIdx.x * blockDim.x + threadIdx.x;
    if (t < TCOUNT) {
        #pragma unroll
        for (int s = 0; s < 2; s++) {
            int e = g_topi[t * 2 + s];
            int pos = g_base[e] + atomicAdd(&g_fill[e], 1);
            g_assign[pos] = t * 2 + s;
        }
    }
}

// ---------------- elementwise -------------------------------------------------
__global__ void silu_mul_kernel(const float* __restrict__ u,
                                const float* __restrict__ g3,
                                __half* __restrict__ act, int n) {
    for (int i = (blockIdx.x * blockDim.x + threadIdx.x) * 2; i < n;
         i += gridDim.x * blockDim.x * 2) {
        float2 a = *(const float2*)(u + i);
        float2 g = *(const float2*)(g3 + i);
        float v0 = (a.x / (1.f + __expf(-a.x))) * g.x;
        float v1 = (a.y / (1.f + __expf(-a.y))) * g.y;
        *(__half2*)(act + i) = __floats2half2_rn(v0, v1);
    }
}

__global__ void final_add_kernel(const float* __restrict__ y,
                                 float* __restrict__ out, int n) {
    for (int i = blockIdx.x * blockDim.x + threadIdx.x; i < n;
         i += gridDim.x * blockDim.x) {
        out[i] = y[i] + g_moe[i] + g_moe[(size_t)TCOUNT * MDIM + i];
    }
}

// ---------------- launch ------------------------------------------------------
extern "C" void kernel_launch(void* const* d_in, const int* in_sizes, int n_in,
                              void* d_out, int out_size) {
    const float* x     = (const float*)d_in[0];
    const float* ln1g  = (const float*)d_in[1];
    const float* ln1b  = (const float*)d_in[2];
    const float* qkvw  = (const float*)d_in[3];
    const float* qkvb  = (const float*)d_in[4];
    const float* ow    = (const float*)d_in[5];
    const float* ob    = (const float*)d_in[6];
    const float* ln2g  = (const float*)d_in[7];
    const float* ln2b  = (const float*)d_in[8];
    const float* gatew = (const float*)d_in[9];
    const float* w1    = (const float*)d_in[10];
    const float* w2    = (const float*)d_in[11];
    const float* w3    = (const float*)d_in[12];
    float* out = (float*)d_out;

    cudaFuncSetAttribute(hmma_gemm<0>,
                         cudaFuncAttributeMaxDynamicSharedMemorySize, GSMEM_B);
    cudaFuncSetAttribute(hmma_gemm<1>,
                         cudaFuncAttributeMaxDynamicSharedMemorySize, GSMEM_B);
    cudaFuncSetAttribute(hmma_gemm<2>,
                         cudaFuncAttributeMaxDynamicSharedMemorySize, GSMEM_B);
    cudaFuncSetAttribute(hmma_gemm<3>,
                         cudaFuncAttributeMaxDynamicSharedMemorySize, GSMEM_B);

    void *h16, *ctx16, *h216, *act16, *qkv16;
    void *qw16, *ow16, *w116, *w316, *w216;
    cudaGetSymbolAddress(&h16, g_h16);
    cudaGetSymbolAddress(&ctx16, g_ctx16);
    cudaGetSymbolAddress(&h216, g_h216);
    cudaGetSymbolAddress(&act16, g_act16);
    cudaGetSymbolAddress(&qkv16, g_qkv16);
    cudaGetSymbolAddress(&qw16, g_qkvw16);
    cudaGetSymbolAddress(&ow16, g_ow16);
    cudaGetSymbolAddress(&w116, g_w116);
    cudaGetSymbolAddress(&w316, g_w316);
    cudaGetSymbolAddress(&w216, g_w216);
    void *yp, *h2p, *up, *g3p;
    cudaGetSymbolAddress(&yp, g_y);
    cudaGetSymbolAddress(&h2p, g_h2);
    cudaGetSymbolAddress(&up, g_u);
    cudaGetSymbolAddress(&g3p, g_g3);

    // (0) zero counters
    zero_cnt_kernel<<<1, 32>>>();
    // (1) all weight conversions in one launch (fp32 -> fp16)
    cvt_all_kernel<<<8192, 256>>>(qkvw, ow, w1, w3, w2);
    // (2) h = LN1(x) -> fp16
    ln_kernel<<<TCOUNT, 256>>>(x, ln1g, ln1b, nullptr, (__half*)h16);
    // (3) qkv = h @ qkvw^T + qkvb -> fp16
    hmma_gemm<3><<<dim3(NQKV / 128, TCOUNT / 128), 256, GSMEM_B>>>(
        (__half*)h16, (__half*)qw16, qkvb, nullptr, (float*)qkv16, NQKV, MDIM);
    // (4) tensor-core causal flash attention -> ctx fp16
    attn_mma<<<dim3(SLEN / 128, NHEAD, BATCH), 256>>>(
        (__half*)qkv16, (__half*)ctx16);
    // (5) y = x + ctx @ ow^T + ob    <-- ncu capture target
    hmma_gemm<0><<<dim3(MDIM / 128, TCOUNT / 128), 256, GSMEM_B>>>(
        (__half*)ctx16, (__half*)ow16, ob, x, (float*)yp, MDIM, MDIM);
    // (6) h2 = LN2(y) -> fp32 + fp16
    ln_kernel<<<TCOUNT, 256>>>((float*)yp, ln2g, ln2b, (float*)h2p, (__half*)h216);
    // (7-9) routing
    route_kernel<<<TCOUNT / 8, 256>>>((float*)h2p, gatew);
    prefix_kernel<<<1, 32>>>();
    assign_kernel<<<TCOUNT / 256, 256>>>();
    // (10,11) u = h2g @ w1^T ; g3 = h2g @ w3^T
    hmma_gemm<1><<<dim3(DFFN / 128, NASSIGN / 128, NEXP), 256, GSMEM_B>>>(
        (__half*)h216, (__half*)w116, nullptr, nullptr, (float*)up, DFFN, MDIM);
    hmma_gemm<1><<<dim3(DFFN / 128, NASSIGN / 128, NEXP), 256, GSMEM_B>>>(
        (__half*)h216, (__half*)w316, nullptr, nullptr, (float*)g3p, DFFN, MDIM);
    // (12) act = silu(u) * g3 -> fp16
    silu_mul_kernel<<<4096, 256>>>((float*)up, (float*)g3p,
                                   (__half*)act16, NASSIGN * DFFN);
    // (13) moe scatter: w * (act @ w2^T)
    hmma_gemm<2><<<dim3(MDIM / 128, NASSIGN / 128, NEXP), 256, GSMEM_B>>>(
        (__half*)act16, (__half*)w216, nullptr, nullptr, nullptr, MDIM, DFFN);
    // (14) out = y + moe0 + moe1
    final_add_kernel<<<4096, 256>>>((float*)yp, out, TCOUNT * MDIM);
}